// round 9
// baseline (speedup 1.0000x reference)
#include <cuda_runtime.h>
#include <cuda_fp16.h>

#define NMAX   100000
#define EMAX   1600000
#define NGRAPH 64
#define NFEAT  128
#define NHID   64
#define NCLASS 10
#define SCAN_B 512

// ---- scratch (allocation-free rule: __device__ globals) ----
__device__ int   g_csrc[EMAX];          // CSR: src ids grouped by dst
__device__ int   g_ecnt[NMAX];          // in-degree (edges only)
__device__ int   g_off[NMAX];           // CSR row offsets (exclusive scan)
__device__ int   g_cursor[NMAX];
__device__ int   g_scan[NMAX];
__device__ int   g_bsum[256];
__device__ int   g_boff[256];
__device__ float g_dinv[NMAX];
__device__ alignas(16) __half g_hs16[(size_t)NMAX * NHID];  // fp16 hs (gather src)
__device__ alignas(16) float  g_accA[(size_t)NMAX * NHID];
__device__ alignas(16) float  g_accB[(size_t)NMAX * NHID];
__device__ float g_gsum[NGRAPH * NHID];
__device__ int   g_gcnt[NGRAPH];

union H8I4 { int4 i; __half2 h[4]; };
union H4U2 { uint2 u; __half2 h[2]; };

// ---------------------------------------------------------------------------
__global__ void k_init(int N) {
    int i = blockIdx.x * blockDim.x + threadIdx.x;
    if (i < N) g_ecnt[i] = 0;
    if (i < NGRAPH * NHID) g_gsum[i] = 0.f;
    if (i < NGRAPH) g_gcnt[i] = 0;
}

__global__ void k_edge_prep(const int* __restrict__ ei, int E, int N) {
    int e = blockIdx.x * blockDim.x + threadIdx.x;
    if (e >= E) return;
    int s = ei[e];
    int d = ei[E + e];
    if ((unsigned)s >= (unsigned)N || (unsigned)d >= (unsigned)N) return;
    atomicAdd(&g_ecnt[d], 1);
}

// ---- 3-kernel exclusive scan of g_ecnt -> g_off -------------------------
__device__ __forceinline__ int block_incl_scan(int v, int tid) {
    __shared__ int wsum[16];
    int lane = tid & 31, w = tid >> 5;
    int x = v;
#pragma unroll
    for (int o = 1; o < 32; o <<= 1) {
        int t = __shfl_up_sync(0xffffffffu, x, o);
        if (lane >= o) x += t;
    }
    if (lane == 31) wsum[w] = x;
    __syncthreads();
    if (w == 0) {
        int y = (lane < (blockDim.x >> 5)) ? wsum[lane] : 0;
#pragma unroll
        for (int o = 1; o < 16; o <<= 1) {
            int t = __shfl_up_sync(0xffffffffu, y, o);
            if (lane >= o) y += t;
        }
        if (lane < 16) wsum[lane] = y;
    }
    __syncthreads();
    return x + (w > 0 ? wsum[w - 1] : 0);
}

__global__ void k_scanA(int N) {
    int i = blockIdx.x * SCAN_B + threadIdx.x;
    int v = (i < N) ? g_ecnt[i] : 0;
    int incl = block_incl_scan(v, threadIdx.x);
    if (i < N) g_scan[i] = incl - v;
    if (threadIdx.x == SCAN_B - 1) g_bsum[blockIdx.x] = incl;
}

__global__ void k_scanB(int nb) {
    int t = threadIdx.x;
    int v = (t < nb) ? g_bsum[t] : 0;
    int incl = block_incl_scan(v, t);
    if (t < 256) g_boff[t] = incl - v;
}

__global__ void k_scanC(int N) {
    int i = blockIdx.x * SCAN_B + threadIdx.x;
    if (i >= N) return;
    int off = g_scan[i] + g_boff[blockIdx.x];
    g_off[i] = off;
    g_cursor[i] = off;
    g_dinv[i] = rsqrtf((float)(g_ecnt[i] + 1));   // +1 self-loop
}

__global__ void k_csr_fill(const int* __restrict__ ei, int E, int N) {
    int e = blockIdx.x * blockDim.x + threadIdx.x;
    if (e >= E) return;
    int s = ei[e];
    int d = ei[E + e];
    if ((unsigned)s >= (unsigned)N || (unsigned)d >= (unsigned)N) return;
    int pos = atomicAdd(&g_cursor[d], 1);
    g_csrc[pos] = s;
}

// ---------------------------------------------------------------------------
// GEMM epilogue: scale 4 cols by dv, convert to fp16, store 8B.
__device__ __forceinline__ void store_hs16(int n, int cg, float dv, float4 o) {
    H4U2 u;
    u.h[0] = __floats2half2_rn(o.x * dv, o.y * dv);
    u.h[1] = __floats2half2_rn(o.z * dv, o.w * dv);
    reinterpret_cast<uint2*>(g_hs16)[(size_t)n * 16 + cg] = u.u;
}

// Layer 1 GEMM: hs16[n] = fp16(x[n] @ W1)  -- UNSCALED (dinv applied in agg).
// No dependence on prep chain => runs concurrently on a second stream.
__global__ void k_gemm1(const float* __restrict__ x, const float* __restrict__ W, int N) {
    __shared__ float4 Wsh[NFEAT * 16];   // [k][c4]  32KB
    __shared__ float4 xsh[32 * 32];      // [node][k4] 16KB
    int tid = threadIdx.x;
    const float4* W4 = reinterpret_cast<const float4*>(W);
    const float4* x4 = reinterpret_cast<const float4*>(x);
#pragma unroll
    for (int i = tid; i < NFEAT * 16; i += 128) Wsh[i] = W4[i];
    int nb = blockIdx.x * 32;
#pragma unroll
    for (int i = tid; i < 32 * 32; i += 128) {
        int n = nb + (i >> 5);
        xsh[i] = (n < N) ? x4[(size_t)n * 32 + (i & 31)]
                         : make_float4(0.f, 0.f, 0.f, 0.f);
    }
    __syncthreads();

    int cg = tid & 15;
    int ng = tid >> 4;
    float4 a[4];
#pragma unroll
    for (int j = 0; j < 4; j++) a[j] = make_float4(0.f, 0.f, 0.f, 0.f);

#pragma unroll 4
    for (int k4 = 0; k4 < 32; k4++) {
        float4 w0 = Wsh[(4 * k4 + 0) * 16 + cg];
        float4 w1 = Wsh[(4 * k4 + 1) * 16 + cg];
        float4 w2 = Wsh[(4 * k4 + 2) * 16 + cg];
        float4 w3 = Wsh[(4 * k4 + 3) * 16 + cg];
#pragma unroll
        for (int j = 0; j < 4; j++) {
            float4 xv = xsh[(ng * 4 + j) * 32 + k4];
            a[j].x = fmaf(xv.x, w0.x, a[j].x); a[j].y = fmaf(xv.x, w0.y, a[j].y);
            a[j].z = fmaf(xv.x, w0.z, a[j].z); a[j].w = fmaf(xv.x, w0.w, a[j].w);
            a[j].x = fmaf(xv.y, w1.x, a[j].x); a[j].y = fmaf(xv.y, w1.y, a[j].y);
            a[j].z = fmaf(xv.y, w1.z, a[j].z); a[j].w = fmaf(xv.y, w1.w, a[j].w);
            a[j].x = fmaf(xv.z, w2.x, a[j].x); a[j].y = fmaf(xv.z, w2.y, a[j].y);
            a[j].z = fmaf(xv.z, w2.z, a[j].z); a[j].w = fmaf(xv.z, w2.w, a[j].w);
            a[j].x = fmaf(xv.w, w3.x, a[j].x); a[j].y = fmaf(xv.w, w3.y, a[j].y);
            a[j].z = fmaf(xv.w, w3.z, a[j].z); a[j].w = fmaf(xv.w, w3.w, a[j].w);
        }
    }
#pragma unroll
    for (int j = 0; j < 4; j++) {
        int n = nb + ng * 4 + j;
        if (n < N) store_hs16(n, cg, 1.0f, a[j]);   // unscaled
    }
}

// Layers 2/3 GEMM: in = relu(dinv*accPrev + bPrev); hs16 = fp16(dinv*(in @ W)).
__global__ void k_gemm23(const float* __restrict__ accPrev, const float* __restrict__ bPrev,
                         const float* __restrict__ W, int N) {
    __shared__ float4 Wsh[NHID * 16];    // 16KB
    __shared__ float4 xsh[32 * 16];      // 8KB
    int tid = threadIdx.x;
    const float4* W4 = reinterpret_cast<const float4*>(W);
    const float4* acc4 = reinterpret_cast<const float4*>(accPrev);
    const float4* b4p = reinterpret_cast<const float4*>(bPrev);
#pragma unroll
    for (int i = tid; i < NHID * 16; i += 128) Wsh[i] = W4[i];
    int nb = blockIdx.x * 32;
#pragma unroll
    for (int i = tid; i < 32 * 16; i += 128) {
        int n = nb + (i >> 4);
        int k4 = i & 15;
        float4 o = make_float4(0.f, 0.f, 0.f, 0.f);
        if (n < N) {
            float4 av = acc4[(size_t)n * 16 + k4];
            float4 bb = b4p[k4];
            float dv = g_dinv[n];
            o.x = fmaxf(fmaf(dv, av.x, bb.x), 0.f);
            o.y = fmaxf(fmaf(dv, av.y, bb.y), 0.f);
            o.z = fmaxf(fmaf(dv, av.z, bb.z), 0.f);
            o.w = fmaxf(fmaf(dv, av.w, bb.w), 0.f);
        }
        xsh[i] = o;
    }
    __syncthreads();

    int cg = tid & 15;
    int ng = tid >> 4;
    float4 a[4];
#pragma unroll
    for (int j = 0; j < 4; j++) a[j] = make_float4(0.f, 0.f, 0.f, 0.f);

#pragma unroll 4
    for (int k4 = 0; k4 < 16; k4++) {
        float4 w0 = Wsh[(4 * k4 + 0) * 16 + cg];
        float4 w1 = Wsh[(4 * k4 + 1) * 16 + cg];
        float4 w2 = Wsh[(4 * k4 + 2) * 16 + cg];
        float4 w3 = Wsh[(4 * k4 + 3) * 16 + cg];
#pragma unroll
        for (int j = 0; j < 4; j++) {
            float4 xv = xsh[(ng * 4 + j) * 16 + k4];
            a[j].x = fmaf(xv.x, w0.x, a[j].x); a[j].y = fmaf(xv.x, w0.y, a[j].y);
            a[j].z = fmaf(xv.x, w0.z, a[j].z); a[j].w = fmaf(xv.x, w0.w, a[j].w);
            a[j].x = fmaf(xv.y, w1.x, a[j].x); a[j].y = fmaf(xv.y, w1.y, a[j].y);
            a[j].z = fmaf(xv.y, w1.z, a[j].z); a[j].w = fmaf(xv.y, w1.w, a[j].w);
            a[j].x = fmaf(xv.z, w2.x, a[j].x); a[j].y = fmaf(xv.z, w2.y, a[j].y);
            a[j].z = fmaf(xv.z, w2.z, a[j].z); a[j].w = fmaf(xv.z, w2.w, a[j].w);
            a[j].x = fmaf(xv.w, w3.x, a[j].x); a[j].y = fmaf(xv.w, w3.y, a[j].y);
            a[j].z = fmaf(xv.w, w3.z, a[j].z); a[j].w = fmaf(xv.w, w3.w, a[j].w);
        }
    }
#pragma unroll
    for (int j = 0; j < 4; j++) {
        int n = nb + ng * 4 + j;
        if (n < N) store_hs16(n, cg, g_dinv[n], a[j]);
    }
}

// ---------------------------------------------------------------------------
// CSR gather aggregation (fp16 source, HADD2/HFMA2 slot accumulate, fp32 reduce).
// SCALE_SRC: multiply each gathered row by dinv[s] (layer 1, unscaled hs).
template<bool SCALE_SRC>
__global__ void k_agg(float* __restrict__ accOut, int N) {
    int warp = (blockIdx.x * blockDim.x + threadIdx.x) >> 5;
    if (warp >= N) return;
    int lane = threadIdx.x & 31;
    int p = lane & 7;        // 16B chunk (cols p*8 .. p*8+7)
    int q = lane >> 3;       // edge slot 0..3
    const int4* h16 = reinterpret_cast<const int4*>(g_hs16);
    const int* __restrict__ csrc = g_csrc;
    int n = warp;
    int start = g_off[n];
    int end = start + g_ecnt[n];

    __half2 a[4];
    if (q == 0) {            // self-loop init (scaled by dinv[n] if needed)
        H8I4 v; v.i = h16[(size_t)n * 8 + p];
        if (SCALE_SRC) {
            __half2 dn = __float2half2_rn(g_dinv[n]);
#pragma unroll
            for (int i = 0; i < 4; i++) a[i] = __hmul2(v.h[i], dn);
        } else {
#pragma unroll
            for (int i = 0; i < 4; i++) a[i] = v.h[i];
        }
    } else {
#pragma unroll
        for (int i = 0; i < 4; i++) a[i] = __half2half2(__ushort_as_half(0));
    }
    int j = start + q;
    for (; j + 12 < end; j += 16) {
        int s0 = csrc[j], s1 = csrc[j + 4], s2 = csrc[j + 8], s3 = csrc[j + 12];
        H8I4 v0; v0.i = h16[(size_t)s0 * 8 + p];
        H8I4 v1; v1.i = h16[(size_t)s1 * 8 + p];
        H8I4 v2; v2.i = h16[(size_t)s2 * 8 + p];
        H8I4 v3; v3.i = h16[(size_t)s3 * 8 + p];
        if (SCALE_SRC) {
            __half2 d0 = __float2half2_rn(g_dinv[s0]);
            __half2 d1 = __float2half2_rn(g_dinv[s1]);
            __half2 d2 = __float2half2_rn(g_dinv[s2]);
            __half2 d3 = __float2half2_rn(g_dinv[s3]);
#pragma unroll
            for (int i = 0; i < 4; i++) {
                a[i] = __hfma2(v0.h[i], d0, a[i]);
                a[i] = __hfma2(v1.h[i], d1, a[i]);
                a[i] = __hfma2(v2.h[i], d2, a[i]);
                a[i] = __hfma2(v3.h[i], d3, a[i]);
            }
        } else {
#pragma unroll
            for (int i = 0; i < 4; i++) {
                a[i] = __hadd2(a[i], v0.h[i]);
                a[i] = __hadd2(a[i], v1.h[i]);
                a[i] = __hadd2(a[i], v2.h[i]);
                a[i] = __hadd2(a[i], v3.h[i]);
            }
        }
    }
    for (; j < end; j += 4) {
        int s = csrc[j];
        H8I4 v; v.i = h16[(size_t)s * 8 + p];
        if (SCALE_SRC) {
            __half2 d = __float2half2_rn(g_dinv[s]);
#pragma unroll
            for (int i = 0; i < 4; i++) a[i] = __hfma2(v.h[i], d, a[i]);
        } else {
#pragma unroll
            for (int i = 0; i < 4; i++) a[i] = __hadd2(a[i], v.h[i]);
        }
    }
    // convert to fp32, reduce across the 4 edge slots in fp32
    float f[8];
#pragma unroll
    for (int i = 0; i < 4; i++) {
        float2 t = __half22float2(a[i]);
        f[2 * i] = t.x; f[2 * i + 1] = t.y;
    }
    const unsigned F = 0xffffffffu;
#pragma unroll
    for (int off = 8; off <= 16; off <<= 1) {
#pragma unroll
        for (int i = 0; i < 8; i++) f[i] += __shfl_xor_sync(F, f[i], off);
    }
    if (lane < 8) {
        float4* out4 = reinterpret_cast<float4*>(accOut);
        out4[(size_t)n * 16 + lane * 2]     = make_float4(f[0], f[1], f[2], f[3]);
        out4[(size_t)n * 16 + lane * 2 + 1] = make_float4(f[4], f[5], f[6], f[7]);
    }
}

// ---------------------------------------------------------------------------
__global__ void k_pool(const float* __restrict__ acc3, const float* __restrict__ b3,
                       const int* __restrict__ batch, int N) {
    int t = blockIdx.x * blockDim.x + threadIdx.x;
    int c = t & 63;
    int n0 = (t >> 6) * 4;
    if (n0 >= N) return;
    float b = b3[c];
    float accum = 0.f;
    int cnt = 0;
    int gprev = -1;
    for (int j = 0; j < 4; j++) {
        int n = n0 + j;
        if (n >= N) break;
        int g = batch[n];
        if ((unsigned)g >= NGRAPH) continue;
        if (g != gprev) {
            if (gprev >= 0) {
                atomicAdd(&g_gsum[gprev * NHID + c], accum);
                if (c == 0) atomicAdd(&g_gcnt[gprev], cnt);
            }
            accum = 0.f; cnt = 0; gprev = g;
        }
        accum += fmaxf(fmaf(g_dinv[n], acc3[(size_t)n * NHID + c], b), 0.f);
        cnt++;
    }
    if (gprev >= 0) {
        atomicAdd(&g_gsum[gprev * NHID + c], accum);
        if (c == 0) atomicAdd(&g_gcnt[gprev], cnt);
    }
}

__global__ void k_head(const float* __restrict__ Wl, const float* __restrict__ bl,
                       float* __restrict__ out) {
    int g = threadIdx.x;
    if (g >= NGRAPH) return;
    float cnt = fmaxf((float)g_gcnt[g], 1.f);
    float inv = 1.f / cnt;
    float l[NCLASS];
#pragma unroll
    for (int c = 0; c < NCLASS; c++) l[c] = bl[c];
    for (int k = 0; k < NHID; k++) {
        float p = g_gsum[g * NHID + k] * inv;
#pragma unroll
        for (int c = 0; c < NCLASS; c++) l[c] = fmaf(p, Wl[k * NCLASS + c], l[c]);
    }
    float m = l[0];
#pragma unroll
    for (int c = 1; c < NCLASS; c++) m = fmaxf(m, l[c]);
    float s = 0.f;
#pragma unroll
    for (int c = 0; c < NCLASS; c++) { l[c] = __expf(l[c] - m); s += l[c]; }
    float is = 1.f / s;
#pragma unroll
    for (int c = 0; c < NCLASS; c++) out[g * NCLASS + c] = l[c] * is;
}

// ---------------------------------------------------------------------------
extern "C" void kernel_launch(void* const* d_in, const int* in_sizes, int n_in,
                              void* d_out, int out_size) {
    const float* x     = (const float*)d_in[0];
    const int*   ei    = (const int*)d_in[1];
    const int*   batch = (const int*)d_in[2];
    const float* W1 = (const float*)d_in[3];
    const float* b1 = (const float*)d_in[4];
    const float* W2 = (const float*)d_in[5];
    const float* b2 = (const float*)d_in[6];
    const float* W3 = (const float*)d_in[7];
    const float* b3 = (const float*)d_in[8];
    const float* Wl = (const float*)d_in[9];
    const float* bl = (const float*)d_in[10];
    float* out = (float*)d_out;

    int N = in_sizes[0] / NFEAT;
    int E = in_sizes[1] / 2;

    float *accA = nullptr, *accB = nullptr;
    cudaGetSymbolAddress((void**)&accA, g_accA);
    cudaGetSymbolAddress((void**)&accB, g_accB);

    // Lazy one-time stream/event creation (first call is the uncaptured
    // correctness run; no device memory is allocated by these).
    static cudaStream_t s2 = nullptr;
    static cudaEvent_t evF = nullptr, evJ = nullptr;
    if (s2 == nullptr) {
        cudaStreamCreateWithFlags(&s2, cudaStreamNonBlocking);
        cudaEventCreateWithFlags(&evF, cudaEventDisableTiming);
        cudaEventCreateWithFlags(&evJ, cudaEventDisableTiming);
    }

    const int T = 256;
    int nScanBlocks = (N + SCAN_B - 1) / SCAN_B;
    int gemmBlocks = (N + 31) / 32;
    int aggBlocks = (N * 32 + T - 1) / T;

    // Fork: gemm1 (x @ W1, unscaled) runs concurrently with the prep chain.
    cudaEventRecord(evF, 0);
    cudaStreamWaitEvent(s2, evF, 0);
    k_gemm1<<<gemmBlocks, 128, 0, s2>>>(x, W1, N);
    cudaEventRecord(evJ, s2);

    // Prep chain on default stream.
    k_init<<<(N + T - 1) / T, T>>>(N);
    k_edge_prep<<<(E + T - 1) / T, T>>>(ei, E, N);
    k_scanA<<<nScanBlocks, SCAN_B>>>(N);
    k_scanB<<<1, 256>>>(nScanBlocks);
    k_scanC<<<nScanBlocks, SCAN_B>>>(N);
    k_csr_fill<<<(E + T - 1) / T, T>>>(ei, E, N);

    // Join: layer-1 agg needs both CSR and gemm1 output.
    cudaStreamWaitEvent(0, evJ, 0);

    // Layer 1 (dinv[s] applied during gather)
    k_agg<true><<<aggBlocks, T>>>(accA, N);
    // Layer 2
    k_gemm23<<<gemmBlocks, 128>>>(accA, b1, W2, N);
    k_agg<false><<<aggBlocks, T>>>(accB, N);
    // Layer 3
    k_gemm23<<<gemmBlocks, 128>>>(accB, b2, W3, N);
    k_agg<false><<<aggBlocks, T>>>(accA, N);

    // Pool + head
    k_pool<<<(((N + 3) / 4) * 64 + T - 1) / T, T>>>(accA, b3, batch, N);
    k_head<<<1, 64>>>(Wl, bl, out);
}

// round 10
// speedup vs baseline: 1.0072x; 1.0072x over previous
#include <cuda_runtime.h>
#include <cuda_fp16.h>

#define NMAX   100000
#define EMAX   1600000
#define NGRAPH 64
#define NFEAT  128
#define NHID   64
#define NCLASS 10
#define SCAN_B 512

// ---- scratch (allocation-free rule: __device__ globals) ----
__device__ int   g_csrc[EMAX];          // CSR: src ids grouped by dst
__device__ int   g_ecnt[NMAX];          // in-degree (edges only)
__device__ int   g_off[NMAX];           // CSR row offsets (exclusive scan)
__device__ int   g_cursor[NMAX];
__device__ int   g_scan[NMAX];
__device__ int   g_bsum[256];
__device__ int   g_boff[256];
__device__ float g_dinv[NMAX];
__device__ alignas(16) __half g_hs16[(size_t)NMAX * NHID];  // fp16 hs (gather src)
__device__ alignas(16) float  g_accA[(size_t)NMAX * NHID];
__device__ alignas(16) float  g_accB[(size_t)NMAX * NHID];
__device__ float g_gsum[NGRAPH * NHID];
__device__ int   g_gcnt[NGRAPH];

union H8I4 { int4 i; __half2 h[4]; };
union H4U2 { uint2 u; __half2 h[2]; };
union F4U2 { float4 f; unsigned long long u[2]; };

// ---- f32x2 packed-math helpers (fp32-exact; FFMA2 only via PTX) -----------
__device__ __forceinline__ unsigned long long ffma2(unsigned long long a,
                                                    unsigned long long b,
                                                    unsigned long long c) {
    unsigned long long d;
    asm("fma.rn.f32x2 %0, %1, %2, %3;" : "=l"(d) : "l"(a), "l"(b), "l"(c));
    return d;
}
__device__ __forceinline__ unsigned long long bcast2(float x) {
    unsigned long long d;
    asm("mov.b64 %0, {%1, %1};" : "=l"(d) : "f"(x));
    return d;
}
__device__ __forceinline__ void unpack2(unsigned long long p, float& lo, float& hi) {
    asm("mov.b64 {%0, %1}, %2;" : "=f"(lo), "=f"(hi) : "l"(p));
}

// ---------------------------------------------------------------------------
__global__ void k_init(int N) {
    int i = blockIdx.x * blockDim.x + threadIdx.x;
    if (i < N) g_ecnt[i] = 0;
    if (i < NGRAPH * NHID) g_gsum[i] = 0.f;
    if (i < NGRAPH) g_gcnt[i] = 0;
}

__global__ void k_edge_prep(const int* __restrict__ ei, int E, int N) {
    int e = blockIdx.x * blockDim.x + threadIdx.x;
    if (e >= E) return;
    int s = ei[e];
    int d = ei[E + e];
    if ((unsigned)s >= (unsigned)N || (unsigned)d >= (unsigned)N) return;
    atomicAdd(&g_ecnt[d], 1);
}

// ---- 3-kernel exclusive scan of g_ecnt -> g_off -------------------------
__device__ __forceinline__ int block_incl_scan(int v, int tid) {
    __shared__ int wsum[16];
    int lane = tid & 31, w = tid >> 5;
    int x = v;
#pragma unroll
    for (int o = 1; o < 32; o <<= 1) {
        int t = __shfl_up_sync(0xffffffffu, x, o);
        if (lane >= o) x += t;
    }
    if (lane == 31) wsum[w] = x;
    __syncthreads();
    if (w == 0) {
        int y = (lane < (blockDim.x >> 5)) ? wsum[lane] : 0;
#pragma unroll
        for (int o = 1; o < 16; o <<= 1) {
            int t = __shfl_up_sync(0xffffffffu, y, o);
            if (lane >= o) y += t;
        }
        if (lane < 16) wsum[lane] = y;
    }
    __syncthreads();
    return x + (w > 0 ? wsum[w - 1] : 0);
}

__global__ void k_scanA(int N) {
    int i = blockIdx.x * SCAN_B + threadIdx.x;
    int v = (i < N) ? g_ecnt[i] : 0;
    int incl = block_incl_scan(v, threadIdx.x);
    if (i < N) g_scan[i] = incl - v;
    if (threadIdx.x == SCAN_B - 1) g_bsum[blockIdx.x] = incl;
}

__global__ void k_scanB(int nb) {
    int t = threadIdx.x;
    int v = (t < nb) ? g_bsum[t] : 0;
    int incl = block_incl_scan(v, t);
    if (t < 256) g_boff[t] = incl - v;
}

__global__ void k_scanC(int N) {
    int i = blockIdx.x * SCAN_B + threadIdx.x;
    if (i >= N) return;
    int off = g_scan[i] + g_boff[blockIdx.x];
    g_off[i] = off;
    g_cursor[i] = off;
    g_dinv[i] = rsqrtf((float)(g_ecnt[i] + 1));   // +1 self-loop
}

__global__ void k_csr_fill(const int* __restrict__ ei, int E, int N) {
    int e = blockIdx.x * blockDim.x + threadIdx.x;
    if (e >= E) return;
    int s = ei[e];
    int d = ei[E + e];
    if ((unsigned)s >= (unsigned)N || (unsigned)d >= (unsigned)N) return;
    int pos = atomicAdd(&g_cursor[d], 1);
    g_csrc[pos] = s;
}

// ---------------------------------------------------------------------------
// GEMM epilogue: unpack 2 f32x2 pairs, scale by dinv, fp16, store 8B.
__device__ __forceinline__ void store_hs16_p(int n, int cg, float dv,
                                             unsigned long long p0,
                                             unsigned long long p1) {
    float ax, ay, az, aw;
    unpack2(p0, ax, ay);
    unpack2(p1, az, aw);
    H4U2 u;
    u.h[0] = __floats2half2_rn(ax * dv, ay * dv);
    u.h[1] = __floats2half2_rn(az * dv, aw * dv);
    reinterpret_cast<uint2*>(g_hs16)[(size_t)n * 16 + cg] = u.u;
}

// Layer 1 GEMM: hs16[n] = fp16(dinv[n] * (x[n] @ W1)).
// Same tiling/LDS pattern as R8; mainloop FMAs packed as f32x2 (fp32-exact).
__global__ void k_gemm1(const float* __restrict__ x, const float* __restrict__ W, int N) {
    __shared__ float4 Wsh[NFEAT * 16];   // [k][c4]  32KB
    __shared__ float4 xsh[32 * 32];      // [node][k4] 16KB
    int tid = threadIdx.x;
    const float4* W4 = reinterpret_cast<const float4*>(W);
    const float4* x4 = reinterpret_cast<const float4*>(x);
#pragma unroll
    for (int i = tid; i < NFEAT * 16; i += 128) Wsh[i] = W4[i];
    int nb = blockIdx.x * 32;
#pragma unroll
    for (int i = tid; i < 32 * 32; i += 128) {
        int n = nb + (i >> 5);
        xsh[i] = (n < N) ? x4[(size_t)n * 32 + (i & 31)]
                         : make_float4(0.f, 0.f, 0.f, 0.f);
    }
    __syncthreads();

    int cg = tid & 15;        // col group: cols cg*4..cg*4+3 (2 f32x2 pairs)
    int ng = tid >> 4;        // node group: nodes ng*4..ng*4+3
    unsigned long long a[4][2];
#pragma unroll
    for (int j = 0; j < 4; j++) { a[j][0] = 0ull; a[j][1] = 0ull; }

#pragma unroll 4
    for (int k4 = 0; k4 < 32; k4++) {
        F4U2 w0, w1, w2, w3;
        w0.f = Wsh[(4 * k4 + 0) * 16 + cg];
        w1.f = Wsh[(4 * k4 + 1) * 16 + cg];
        w2.f = Wsh[(4 * k4 + 2) * 16 + cg];
        w3.f = Wsh[(4 * k4 + 3) * 16 + cg];
#pragma unroll
        for (int j = 0; j < 4; j++) {
            float4 xv = xsh[(ng * 4 + j) * 32 + k4];
            unsigned long long p;
            p = bcast2(xv.x);
            a[j][0] = ffma2(p, w0.u[0], a[j][0]); a[j][1] = ffma2(p, w0.u[1], a[j][1]);
            p = bcast2(xv.y);
            a[j][0] = ffma2(p, w1.u[0], a[j][0]); a[j][1] = ffma2(p, w1.u[1], a[j][1]);
            p = bcast2(xv.z);
            a[j][0] = ffma2(p, w2.u[0], a[j][0]); a[j][1] = ffma2(p, w2.u[1], a[j][1]);
            p = bcast2(xv.w);
            a[j][0] = ffma2(p, w3.u[0], a[j][0]); a[j][1] = ffma2(p, w3.u[1], a[j][1]);
        }
    }
#pragma unroll
    for (int j = 0; j < 4; j++) {
        int n = nb + ng * 4 + j;
        if (n < N) store_hs16_p(n, cg, g_dinv[n], a[j][0], a[j][1]);
    }
}

// Layers 2/3 GEMM: in = relu(dinv*accPrev + bPrev); hs16 = fp16(dinv*(in @ W)).
__global__ void k_gemm23(const float* __restrict__ accPrev, const float* __restrict__ bPrev,
                         const float* __restrict__ W, int N) {
    __shared__ float4 Wsh[NHID * 16];    // 16KB
    __shared__ float4 xsh[32 * 16];      // 8KB
    int tid = threadIdx.x;
    const float4* W4 = reinterpret_cast<const float4*>(W);
    const float4* acc4 = reinterpret_cast<const float4*>(accPrev);
    const float4* b4p = reinterpret_cast<const float4*>(bPrev);
#pragma unroll
    for (int i = tid; i < NHID * 16; i += 128) Wsh[i] = W4[i];
    int nb = blockIdx.x * 32;
#pragma unroll
    for (int i = tid; i < 32 * 16; i += 128) {
        int n = nb + (i >> 4);
        int k4 = i & 15;
        float4 o = make_float4(0.f, 0.f, 0.f, 0.f);
        if (n < N) {
            float4 av = acc4[(size_t)n * 16 + k4];
            float4 bb = b4p[k4];
            float dv = g_dinv[n];
            o.x = fmaxf(fmaf(dv, av.x, bb.x), 0.f);
            o.y = fmaxf(fmaf(dv, av.y, bb.y), 0.f);
            o.z = fmaxf(fmaf(dv, av.z, bb.z), 0.f);
            o.w = fmaxf(fmaf(dv, av.w, bb.w), 0.f);
        }
        xsh[i] = o;
    }
    __syncthreads();

    int cg = tid & 15;
    int ng = tid >> 4;
    unsigned long long a[4][2];
#pragma unroll
    for (int j = 0; j < 4; j++) { a[j][0] = 0ull; a[j][1] = 0ull; }

#pragma unroll 4
    for (int k4 = 0; k4 < 16; k4++) {
        F4U2 w0, w1, w2, w3;
        w0.f = Wsh[(4 * k4 + 0) * 16 + cg];
        w1.f = Wsh[(4 * k4 + 1) * 16 + cg];
        w2.f = Wsh[(4 * k4 + 2) * 16 + cg];
        w3.f = Wsh[(4 * k4 + 3) * 16 + cg];
#pragma unroll
        for (int j = 0; j < 4; j++) {
            float4 xv = xsh[(ng * 4 + j) * 16 + k4];
            unsigned long long p;
            p = bcast2(xv.x);
            a[j][0] = ffma2(p, w0.u[0], a[j][0]); a[j][1] = ffma2(p, w0.u[1], a[j][1]);
            p = bcast2(xv.y);
            a[j][0] = ffma2(p, w1.u[0], a[j][0]); a[j][1] = ffma2(p, w1.u[1], a[j][1]);
            p = bcast2(xv.z);
            a[j][0] = ffma2(p, w2.u[0], a[j][0]); a[j][1] = ffma2(p, w2.u[1], a[j][1]);
            p = bcast2(xv.w);
            a[j][0] = ffma2(p, w3.u[0], a[j][0]); a[j][1] = ffma2(p, w3.u[1], a[j][1]);
        }
    }
#pragma unroll
    for (int j = 0; j < 4; j++) {
        int n = nb + ng * 4 + j;
        if (n < N) store_hs16_p(n, cg, g_dinv[n], a[j][0], a[j][1]);
    }
}

// ---------------------------------------------------------------------------
// CSR gather aggregation (fp16 source, HADD2 slot accumulate, fp32 reduce):
// acc[n] = hs[n] (self-loop) + sum_{s in in(n)} hs[s].
// One warp per node; 8 lanes x 16B (8 halves) cover the 128B row; 4 edge slots.
__global__ void k_agg(float* __restrict__ accOut, int N) {
    int warp = (blockIdx.x * blockDim.x + threadIdx.x) >> 5;
    if (warp >= N) return;
    int lane = threadIdx.x & 31;
    int p = lane & 7;        // 16B chunk (cols p*8 .. p*8+7)
    int q = lane >> 3;       // edge slot 0..3
    const int4* h16 = reinterpret_cast<const int4*>(g_hs16);
    const int* __restrict__ csrc = g_csrc;
    int n = warp;
    int start = g_off[n];
    int end = start + g_ecnt[n];

    __half2 a[4];
    if (q == 0) {            // self-loop init
        H8I4 v; v.i = h16[(size_t)n * 8 + p];
#pragma unroll
        for (int i = 0; i < 4; i++) a[i] = v.h[i];
    } else {
#pragma unroll
        for (int i = 0; i < 4; i++) a[i] = __half2half2(__ushort_as_half(0));
    }
    int j = start + q;
    for (; j + 4 < end; j += 8) {
        int sA = csrc[j];
        int sB = csrc[j + 4];
        H8I4 vA; vA.i = h16[(size_t)sA * 8 + p];
        H8I4 vB; vB.i = h16[(size_t)sB * 8 + p];
#pragma unroll
        for (int i = 0; i < 4; i++) a[i] = __hadd2(a[i], vA.h[i]);
#pragma unroll
        for (int i = 0; i < 4; i++) a[i] = __hadd2(a[i], vB.h[i]);
    }
    if (j < end) {
        int s = csrc[j];
        H8I4 v; v.i = h16[(size_t)s * 8 + p];
#pragma unroll
        for (int i = 0; i < 4; i++) a[i] = __hadd2(a[i], v.h[i]);
    }
    // convert to fp32, reduce across the 4 edge slots in fp32
    float f[8];
#pragma unroll
    for (int i = 0; i < 4; i++) {
        float2 t = __half22float2(a[i]);
        f[2 * i] = t.x; f[2 * i + 1] = t.y;
    }
    const unsigned F = 0xffffffffu;
#pragma unroll
    for (int off = 8; off <= 16; off <<= 1) {
#pragma unroll
        for (int i = 0; i < 8; i++) f[i] += __shfl_xor_sync(F, f[i], off);
    }
    if (lane < 8) {
        float4* out4 = reinterpret_cast<float4*>(accOut);
        out4[(size_t)n * 16 + lane * 2]     = make_float4(f[0], f[1], f[2], f[3]);
        out4[(size_t)n * 16 + lane * 2 + 1] = make_float4(f[4], f[5], f[6], f[7]);
    }
}

// ---------------------------------------------------------------------------
// Pool: per-graph sum of relu(dinv*acc3 + b3) with 4-node run-length batching.
__global__ void k_pool(const float* __restrict__ acc3, const float* __restrict__ b3,
                       const int* __restrict__ batch, int N) {
    int t = blockIdx.x * blockDim.x + threadIdx.x;
    int c = t & 63;
    int n0 = (t >> 6) * 4;
    if (n0 >= N) return;
    float b = b3[c];
    float accum = 0.f;
    int cnt = 0;
    int gprev = -1;
    for (int j = 0; j < 4; j++) {
        int n = n0 + j;
        if (n >= N) break;
        int g = batch[n];
        if ((unsigned)g >= NGRAPH) continue;
        if (g != gprev) {
            if (gprev >= 0) {
                atomicAdd(&g_gsum[gprev * NHID + c], accum);
                if (c == 0) atomicAdd(&g_gcnt[gprev], cnt);
            }
            accum = 0.f; cnt = 0; gprev = g;
        }
        accum += fmaxf(fmaf(g_dinv[n], acc3[(size_t)n * NHID + c], b), 0.f);
        cnt++;
    }
    if (gprev >= 0) {
        atomicAdd(&g_gsum[gprev * NHID + c], accum);
        if (c == 0) atomicAdd(&g_gcnt[gprev], cnt);
    }
}

__global__ void k_head(const float* __restrict__ Wl, const float* __restrict__ bl,
                       float* __restrict__ out) {
    int g = threadIdx.x;
    if (g >= NGRAPH) return;
    float cnt = fmaxf((float)g_gcnt[g], 1.f);
    float inv = 1.f / cnt;
    float l[NCLASS];
#pragma unroll
    for (int c = 0; c < NCLASS; c++) l[c] = bl[c];
    for (int k = 0; k < NHID; k++) {
        float p = g_gsum[g * NHID + k] * inv;
#pragma unroll
        for (int c = 0; c < NCLASS; c++) l[c] = fmaf(p, Wl[k * NCLASS + c], l[c]);
    }
    float m = l[0];
#pragma unroll
    for (int c = 1; c < NCLASS; c++) m = fmaxf(m, l[c]);
    float s = 0.f;
#pragma unroll
    for (int c = 0; c < NCLASS; c++) { l[c] = __expf(l[c] - m); s += l[c]; }
    float is = 1.f / s;
#pragma unroll
    for (int c = 0; c < NCLASS; c++) out[g * NCLASS + c] = l[c] * is;
}

// ---------------------------------------------------------------------------
extern "C" void kernel_launch(void* const* d_in, const int* in_sizes, int n_in,
                              void* d_out, int out_size) {
    const float* x     = (const float*)d_in[0];
    const int*   ei    = (const int*)d_in[1];
    const int*   batch = (const int*)d_in[2];
    const float* W1 = (const float*)d_in[3];
    const float* b1 = (const float*)d_in[4];
    const float* W2 = (const float*)d_in[5];
    const float* b2 = (const float*)d_in[6];
    const float* W3 = (const float*)d_in[7];
    const float* b3 = (const float*)d_in[8];
    const float* Wl = (const float*)d_in[9];
    const float* bl = (const float*)d_in[10];
    float* out = (float*)d_out;

    int N = in_sizes[0] / NFEAT;
    int E = in_sizes[1] / 2;

    float *accA = nullptr, *accB = nullptr;
    cudaGetSymbolAddress((void**)&accA, g_accA);
    cudaGetSymbolAddress((void**)&accB, g_accB);

    const int T = 256;
    int nScanBlocks = (N + SCAN_B - 1) / SCAN_B;

    k_init<<<(N + T - 1) / T, T>>>(N);
    k_edge_prep<<<(E + T - 1) / T, T>>>(ei, E, N);
    k_scanA<<<nScanBlocks, SCAN_B>>>(N);
    k_scanB<<<1, 256>>>(nScanBlocks);
    k_scanC<<<nScanBlocks, SCAN_B>>>(N);
    k_csr_fill<<<(E + T - 1) / T, T>>>(ei, E, N);

    int gemmBlocks = (N + 31) / 32;
    int aggBlocks = (N * 32 + T - 1) / T;

    // Layer 1
    k_gemm1<<<gemmBlocks, 128>>>(x, W1, N);
    k_agg<<<aggBlocks, T>>>(accA, N);
    // Layer 2
    k_gemm23<<<gemmBlocks, 128>>>(accA, b1, W2, N);
    k_agg<<<aggBlocks, T>>>(accB, N);
    // Layer 3
    k_gemm23<<<gemmBlocks, 128>>>(accB, b2, W3, N);
    k_agg<<<aggBlocks, T>>>(accA, N);

    // Pool + head
    k_pool<<<(((N + 3) / 4) * 64 + T - 1) / T, T>>>(accA, b3, batch, N);
    k_head<<<1, 64>>>(Wl, bl, out);
}

// round 11
// speedup vs baseline: 1.1663x; 1.1579x over previous
#include <cuda_runtime.h>
#include <cuda_fp16.h>

#define NMAX   100000
#define EMAX   1600000
#define NGRAPH 64
#define NFEAT  128
#define NHID   64
#define NCLASS 10
#define SCAN_B 512

// ---- scratch (allocation-free rule: __device__ globals) ----
__device__ int   g_csrc[EMAX];          // CSR: src ids grouped by dst
__device__ int   g_ecnt[NMAX];          // in-degree (edges only)
__device__ int   g_off[NMAX];           // CSR row offsets (exclusive scan)
__device__ int   g_cursor[NMAX];
__device__ int   g_scan[NMAX];
__device__ int   g_bsum[256];
__device__ int   g_boff[256];
__device__ float g_dinv[NMAX];
__device__ alignas(16) __half g_hs16[(size_t)NMAX * NHID];  // fp16 hs (gather src)
__device__ alignas(16) float  g_accA[(size_t)NMAX * NHID];
__device__ alignas(16) float  g_accB[(size_t)NMAX * NHID];
__device__ float g_gsum[NGRAPH * NHID];
__device__ int   g_gcnt[NGRAPH];

union H8I4 { int4 i; __half2 h[4]; };
union H4U2 { uint2 u; __half2 h[2]; };
union H2U  { unsigned u; __half2 h; };

__device__ __forceinline__ unsigned smem_u32(const void* p) {
    unsigned r;
    asm("{ .reg .u64 t; cvta.to.shared.u64 t, %1; cvt.u32.u64 %0, t; }"
        : "=r"(r) : "l"(p));
    return r;
}

// ---------------------------------------------------------------------------
__global__ void k_init(int N) {
    int i = blockIdx.x * blockDim.x + threadIdx.x;
    if (i < N) g_ecnt[i] = 0;
    if (i < NGRAPH * NHID) g_gsum[i] = 0.f;
    if (i < NGRAPH) g_gcnt[i] = 0;
}

__global__ void k_edge_prep(const int* __restrict__ ei, int E, int N) {
    int e = blockIdx.x * blockDim.x + threadIdx.x;
    if (e >= E) return;
    int s = ei[e];
    int d = ei[E + e];
    if ((unsigned)s >= (unsigned)N || (unsigned)d >= (unsigned)N) return;
    atomicAdd(&g_ecnt[d], 1);
}

// ---- 3-kernel exclusive scan of g_ecnt -> g_off -------------------------
__device__ __forceinline__ int block_incl_scan(int v, int tid) {
    __shared__ int wsum[16];
    int lane = tid & 31, w = tid >> 5;
    int x = v;
#pragma unroll
    for (int o = 1; o < 32; o <<= 1) {
        int t = __shfl_up_sync(0xffffffffu, x, o);
        if (lane >= o) x += t;
    }
    if (lane == 31) wsum[w] = x;
    __syncthreads();
    if (w == 0) {
        int y = (lane < (blockDim.x >> 5)) ? wsum[lane] : 0;
#pragma unroll
        for (int o = 1; o < 16; o <<= 1) {
            int t = __shfl_up_sync(0xffffffffu, y, o);
            if (lane >= o) y += t;
        }
        if (lane < 16) wsum[lane] = y;
    }
    __syncthreads();
    return x + (w > 0 ? wsum[w - 1] : 0);
}

__global__ void k_scanA(int N) {
    int i = blockIdx.x * SCAN_B + threadIdx.x;
    int v = (i < N) ? g_ecnt[i] : 0;
    int incl = block_incl_scan(v, threadIdx.x);
    if (i < N) g_scan[i] = incl - v;
    if (threadIdx.x == SCAN_B - 1) g_bsum[blockIdx.x] = incl;
}

__global__ void k_scanB(int nb) {
    int t = threadIdx.x;
    int v = (t < nb) ? g_bsum[t] : 0;
    int incl = block_incl_scan(v, t);
    if (t < 256) g_boff[t] = incl - v;
}

__global__ void k_scanC(int N) {
    int i = blockIdx.x * SCAN_B + threadIdx.x;
    if (i >= N) return;
    int off = g_scan[i] + g_boff[blockIdx.x];
    g_off[i] = off;
    g_cursor[i] = off;
    g_dinv[i] = rsqrtf((float)(g_ecnt[i] + 1));   // +1 self-loop
}

__global__ void k_csr_fill(const int* __restrict__ ei, int E, int N) {
    int e = blockIdx.x * blockDim.x + threadIdx.x;
    if (e >= E) return;
    int s = ei[e];
    int d = ei[E + e];
    if ((unsigned)s >= (unsigned)N || (unsigned)d >= (unsigned)N) return;
    int pos = atomicAdd(&g_cursor[d], 1);
    g_csrc[pos] = s;
}

// ---------------------------------------------------------------------------
// Layer 1 GEMM via HMMA (m16n8k16, fp16 in / fp32 acc):
//   hs16[n] = fp16(dinv[n] * (x[n] @ W1)).
// 128 threads = 4 warps; 64 nodes x 64 cols per block; K = 128.
// Smem tiles are fp16 with +8-half row padding (ldmatrix conflict-free).
#define XS_LD 136   // 128 + 8 halves
#define WS_LD 72    // 64 + 8 halves
__global__ void k_gemm1(const float* __restrict__ x, const float* __restrict__ W, int N) {
    __shared__ __half xs[64 * XS_LD];    // 17408 B
    __shared__ __half ws[NFEAT * WS_LD]; // 18432 B
    int tid = threadIdx.x;
    int nb = blockIdx.x * 64;
    const float4* x4 = reinterpret_cast<const float4*>(x);
    const float4* W4 = reinterpret_cast<const float4*>(W);

    // W1 [128][64] -> ws fp16
    for (int i = tid; i < NFEAT * 16; i += 128) {
        int k = i >> 4, c4 = i & 15;
        float4 v = W4[i];
        H4U2 u;
        u.h[0] = __floats2half2_rn(v.x, v.y);
        u.h[1] = __floats2half2_rn(v.z, v.w);
        *reinterpret_cast<uint2*>(&ws[k * WS_LD + c4 * 4]) = u.u;
    }
    // x tile [64][128] -> xs fp16
    for (int i = tid; i < 64 * 32; i += 128) {
        int n = i >> 5, c4 = i & 31;
        float4 v = (nb + n < N) ? x4[(size_t)(nb + n) * 32 + c4]
                                : make_float4(0.f, 0.f, 0.f, 0.f);
        H4U2 u;
        u.h[0] = __floats2half2_rn(v.x, v.y);
        u.h[1] = __floats2half2_rn(v.z, v.w);
        *reinterpret_cast<uint2*>(&xs[n * XS_LD + c4 * 4]) = u.u;
    }
    __syncthreads();

    int lane = tid & 31, warp = tid >> 5;
    int m0 = warp * 16;
    int g = lane >> 2, t = lane & 3;
    float c[8][4];
#pragma unroll
    for (int nt = 0; nt < 8; nt++)
#pragma unroll
        for (int r = 0; r < 4; r++) c[nt][r] = 0.f;

    unsigned xs_base = smem_u32(xs);
    unsigned ws_base = smem_u32(ws);
    int aRow = m0 + (lane & 15);
    int aHalf = lane >> 4;

#pragma unroll
    for (int ks = 0; ks < 8; ks++) {
        unsigned aAddr = xs_base + (unsigned)((aRow * XS_LD + ks * 16 + aHalf * 8) * 2);
        unsigned a0, a1, a2, a3;
        asm volatile("ldmatrix.sync.aligned.m8n8.x4.shared.b16 {%0,%1,%2,%3}, [%4];"
                     : "=r"(a0), "=r"(a1), "=r"(a2), "=r"(a3) : "r"(aAddr));
        int bRow = ks * 16 + (lane & 15);
#pragma unroll
        for (int nt = 0; nt < 8; nt++) {
            unsigned bAddr = ws_base + (unsigned)((bRow * WS_LD + nt * 8) * 2);
            unsigned b0, b1;
            asm volatile("ldmatrix.sync.aligned.m8n8.x2.trans.shared.b16 {%0,%1}, [%2];"
                         : "=r"(b0), "=r"(b1) : "r"(bAddr));
            asm volatile(
                "mma.sync.aligned.m16n8k16.row.col.f32.f16.f16.f32 "
                "{%0,%1,%2,%3}, {%4,%5,%6,%7}, {%8,%9}, {%0,%1,%2,%3};"
                : "+f"(c[nt][0]), "+f"(c[nt][1]), "+f"(c[nt][2]), "+f"(c[nt][3])
                : "r"(a0), "r"(a1), "r"(a2), "r"(a3), "r"(b0), "r"(b1));
        }
    }

    int row0 = nb + m0 + g;
    int row1 = row0 + 8;
    float dv0 = (row0 < N) ? g_dinv[row0] : 0.f;
    float dv1 = (row1 < N) ? g_dinv[row1] : 0.f;
    unsigned* hsu = reinterpret_cast<unsigned*>(g_hs16);
#pragma unroll
    for (int nt = 0; nt < 8; nt++) {
        if (row0 < N) {
            H2U u; u.h = __floats2half2_rn(c[nt][0] * dv0, c[nt][1] * dv0);
            hsu[(size_t)row0 * 32 + nt * 4 + t] = u.u;
        }
        if (row1 < N) {
            H2U u; u.h = __floats2half2_rn(c[nt][2] * dv1, c[nt][3] * dv1);
            hsu[(size_t)row1 * 32 + nt * 4 + t] = u.u;
        }
    }
}

// Layers 2/3 GEMM (proven scalar path): in = relu(dinv*accPrev + bPrev);
// hs16 = fp16(dinv * (in @ W)).
__global__ void k_gemm23(const float* __restrict__ accPrev, const float* __restrict__ bPrev,
                         const float* __restrict__ W, int N) {
    __shared__ float4 Wsh[NHID * 16];    // 16KB
    __shared__ float4 xsh[32 * 16];      // 8KB
    int tid = threadIdx.x;
    const float4* W4 = reinterpret_cast<const float4*>(W);
    const float4* acc4 = reinterpret_cast<const float4*>(accPrev);
    const float4* b4p = reinterpret_cast<const float4*>(bPrev);
#pragma unroll
    for (int i = tid; i < NHID * 16; i += 128) Wsh[i] = W4[i];
    int nb = blockIdx.x * 32;
#pragma unroll
    for (int i = tid; i < 32 * 16; i += 128) {
        int n = nb + (i >> 4);
        int k4 = i & 15;
        float4 o = make_float4(0.f, 0.f, 0.f, 0.f);
        if (n < N) {
            float4 av = acc4[(size_t)n * 16 + k4];
            float4 bb = b4p[k4];
            float dv = g_dinv[n];
            o.x = fmaxf(fmaf(dv, av.x, bb.x), 0.f);
            o.y = fmaxf(fmaf(dv, av.y, bb.y), 0.f);
            o.z = fmaxf(fmaf(dv, av.z, bb.z), 0.f);
            o.w = fmaxf(fmaf(dv, av.w, bb.w), 0.f);
        }
        xsh[i] = o;
    }
    __syncthreads();

    int cg = tid & 15;
    int ng = tid >> 4;
    float4 a[4];
#pragma unroll
    for (int j = 0; j < 4; j++) a[j] = make_float4(0.f, 0.f, 0.f, 0.f);

#pragma unroll 4
    for (int k4 = 0; k4 < 16; k4++) {
        float4 w0 = Wsh[(4 * k4 + 0) * 16 + cg];
        float4 w1 = Wsh[(4 * k4 + 1) * 16 + cg];
        float4 w2 = Wsh[(4 * k4 + 2) * 16 + cg];
        float4 w3 = Wsh[(4 * k4 + 3) * 16 + cg];
#pragma unroll
        for (int j = 0; j < 4; j++) {
            float4 xv = xsh[(ng * 4 + j) * 16 + k4];
            a[j].x = fmaf(xv.x, w0.x, a[j].x); a[j].y = fmaf(xv.x, w0.y, a[j].y);
            a[j].z = fmaf(xv.x, w0.z, a[j].z); a[j].w = fmaf(xv.x, w0.w, a[j].w);
            a[j].x = fmaf(xv.y, w1.x, a[j].x); a[j].y = fmaf(xv.y, w1.y, a[j].y);
            a[j].z = fmaf(xv.y, w1.z, a[j].z); a[j].w = fmaf(xv.y, w1.w, a[j].w);
            a[j].x = fmaf(xv.z, w2.x, a[j].x); a[j].y = fmaf(xv.z, w2.y, a[j].y);
            a[j].z = fmaf(xv.z, w2.z, a[j].z); a[j].w = fmaf(xv.z, w2.w, a[j].w);
            a[j].x = fmaf(xv.w, w3.x, a[j].x); a[j].y = fmaf(xv.w, w3.y, a[j].y);
            a[j].z = fmaf(xv.w, w3.z, a[j].z); a[j].w = fmaf(xv.w, w3.w, a[j].w);
        }
    }
#pragma unroll
    for (int j = 0; j < 4; j++) {
        int n = nb + ng * 4 + j;
        if (n < N) {
            float dv = g_dinv[n];
            H4U2 u;
            u.h[0] = __floats2half2_rn(a[j].x * dv, a[j].y * dv);
            u.h[1] = __floats2half2_rn(a[j].z * dv, a[j].w * dv);
            reinterpret_cast<uint2*>(g_hs16)[(size_t)n * 16 + cg] = u.u;
        }
    }
}

// ---------------------------------------------------------------------------
// CSR gather aggregation (fp16 source, HADD2 slot accumulate, fp32 reduce):
// acc[n] = hs[n] (self-loop) + sum_{s in in(n)} hs[s].
__global__ void k_agg(float* __restrict__ accOut, int N) {
    int warp = (blockIdx.x * blockDim.x + threadIdx.x) >> 5;
    if (warp >= N) return;
    int lane = threadIdx.x & 31;
    int p = lane & 7;        // 16B chunk (cols p*8 .. p*8+7)
    int q = lane >> 3;       // edge slot 0..3
    const int4* h16 = reinterpret_cast<const int4*>(g_hs16);
    const int* __restrict__ csrc = g_csrc;
    int n = warp;
    int start = g_off[n];
    int end = start + g_ecnt[n];

    __half2 a[4];
    if (q == 0) {            // self-loop init
        H8I4 v; v.i = h16[(size_t)n * 8 + p];
#pragma unroll
        for (int i = 0; i < 4; i++) a[i] = v.h[i];
    } else {
#pragma unroll
        for (int i = 0; i < 4; i++) a[i] = __half2half2(__ushort_as_half(0));
    }
    int j = start + q;
    for (; j + 4 < end; j += 8) {
        int sA = csrc[j];
        int sB = csrc[j + 4];
        H8I4 vA; vA.i = h16[(size_t)sA * 8 + p];
        H8I4 vB; vB.i = h16[(size_t)sB * 8 + p];
#pragma unroll
        for (int i = 0; i < 4; i++) a[i] = __hadd2(a[i], vA.h[i]);
#pragma unroll
        for (int i = 0; i < 4; i++) a[i] = __hadd2(a[i], vB.h[i]);
    }
    if (j < end) {
        int s = csrc[j];
        H8I4 v; v.i = h16[(size_t)s * 8 + p];
#pragma unroll
        for (int i = 0; i < 4; i++) a[i] = __hadd2(a[i], v.h[i]);
    }
    float f[8];
#pragma unroll
    for (int i = 0; i < 4; i++) {
        float2 t = __half22float2(a[i]);
        f[2 * i] = t.x; f[2 * i + 1] = t.y;
    }
    const unsigned F = 0xffffffffu;
#pragma unroll
    for (int off = 8; off <= 16; off <<= 1) {
#pragma unroll
        for (int i = 0; i < 8; i++) f[i] += __shfl_xor_sync(F, f[i], off);
    }
    if (lane < 8) {
        float4* out4 = reinterpret_cast<float4*>(accOut);
        out4[(size_t)n * 16 + lane * 2]     = make_float4(f[0], f[1], f[2], f[3]);
        out4[(size_t)n * 16 + lane * 2 + 1] = make_float4(f[4], f[5], f[6], f[7]);
    }
}

// ---------------------------------------------------------------------------
__global__ void k_pool(const float* __restrict__ acc3, const float* __restrict__ b3,
                       const int* __restrict__ batch, int N) {
    int t = blockIdx.x * blockDim.x + threadIdx.x;
    int c = t & 63;
    int n0 = (t >> 6) * 4;
    if (n0 >= N) return;
    float b = b3[c];
    float accum = 0.f;
    int cnt = 0;
    int gprev = -1;
    for (int j = 0; j < 4; j++) {
        int n = n0 + j;
        if (n >= N) break;
        int g = batch[n];
        if ((unsigned)g >= NGRAPH) continue;
        if (g != gprev) {
            if (gprev >= 0) {
                atomicAdd(&g_gsum[gprev * NHID + c], accum);
                if (c == 0) atomicAdd(&g_gcnt[gprev], cnt);
            }
            accum = 0.f; cnt = 0; gprev = g;
        }
        accum += fmaxf(fmaf(g_dinv[n], acc3[(size_t)n * NHID + c], b), 0.f);
        cnt++;
    }
    if (gprev >= 0) {
        atomicAdd(&g_gsum[gprev * NHID + c], accum);
        if (c == 0) atomicAdd(&g_gcnt[gprev], cnt);
    }
}

__global__ void k_head(const float* __restrict__ Wl, const float* __restrict__ bl,
                       float* __restrict__ out) {
    int g = threadIdx.x;
    if (g >= NGRAPH) return;
    float cnt = fmaxf((float)g_gcnt[g], 1.f);
    float inv = 1.f / cnt;
    float l[NCLASS];
#pragma unroll
    for (int c = 0; c < NCLASS; c++) l[c] = bl[c];
    for (int k = 0; k < NHID; k++) {
        float p = g_gsum[g * NHID + k] * inv;
#pragma unroll
        for (int c = 0; c < NCLASS; c++) l[c] = fmaf(p, Wl[k * NCLASS + c], l[c]);
    }
    float m = l[0];
#pragma unroll
    for (int c = 1; c < NCLASS; c++) m = fmaxf(m, l[c]);
    float s = 0.f;
#pragma unroll
    for (int c = 0; c < NCLASS; c++) { l[c] = __expf(l[c] - m); s += l[c]; }
    float is = 1.f / s;
#pragma unroll
    for (int c = 0; c < NCLASS; c++) out[g * NCLASS + c] = l[c] * is;
}

// ---------------------------------------------------------------------------
extern "C" void kernel_launch(void* const* d_in, const int* in_sizes, int n_in,
                              void* d_out, int out_size) {
    const float* x     = (const float*)d_in[0];
    const int*   ei    = (const int*)d_in[1];
    const int*   batch = (const int*)d_in[2];
    const float* W1 = (const float*)d_in[3];
    const float* b1 = (const float*)d_in[4];
    const float* W2 = (const float*)d_in[5];
    const float* b2 = (const float*)d_in[6];
    const float* W3 = (const float*)d_in[7];
    const float* b3 = (const float*)d_in[8];
    const float* Wl = (const float*)d_in[9];
    const float* bl = (const float*)d_in[10];
    float* out = (float*)d_out;

    int N = in_sizes[0] / NFEAT;
    int E = in_sizes[1] / 2;

    float *accA = nullptr, *accB = nullptr;
    cudaGetSymbolAddress((void**)&accA, g_accA);
    cudaGetSymbolAddress((void**)&accB, g_accB);

    const int T = 256;
    int nScanBlocks = (N + SCAN_B - 1) / SCAN_B;

    k_init<<<(N + T - 1) / T, T>>>(N);
    k_edge_prep<<<(E + T - 1) / T, T>>>(ei, E, N);
    k_scanA<<<nScanBlocks, SCAN_B>>>(N);
    k_scanB<<<1, 256>>>(nScanBlocks);
    k_scanC<<<nScanBlocks, SCAN_B>>>(N);
    k_csr_fill<<<(E + T - 1) / T, T>>>(ei, E, N);

    int gemm1Blocks = (N + 63) / 64;
    int gemmBlocks = (N + 31) / 32;
    int aggBlocks = (N * 32 + T - 1) / T;

    // Layer 1 (HMMA)
    k_gemm1<<<gemm1Blocks, 128>>>(x, W1, N);
    k_agg<<<aggBlocks, T>>>(accA, N);
    // Layer 2
    k_gemm23<<<gemmBlocks, 128>>>(accA, b1, W2, N);
    k_agg<<<aggBlocks, T>>>(accB, N);
    // Layer 3
    k_gemm23<<<gemmBlocks, 128>>>(accB, b2, W3, N);
    k_agg<<<aggBlocks, T>>>(accA, N);

    // Pool + head
    k_pool<<<(((N + 3) / 4) * 64 + T - 1) / T, T>>>(accA, b3, batch, N);
    k_head<<<1, 64>>>(Wl, bl, out);
}

// round 12
// speedup vs baseline: 1.2771x; 1.0951x over previous
#include <cuda_runtime.h>
#include <cuda_fp16.h>

#define NMAX   100000
#define EMAX   1600000
#define NGRAPH 64
#define NFEAT  128
#define NHID   64
#define NCLASS 10
#define SCAN_B 512

// ---- scratch (allocation-free rule: __device__ globals) ----
__device__ int   g_csrc[EMAX];          // CSR: src ids grouped by dst
__device__ int   g_ecnt[NMAX];          // in-degree (edges only)
__device__ int   g_off[NMAX];           // CSR row offsets (exclusive scan)
__device__ int   g_cursor[NMAX];
__device__ int   g_scan[NMAX];
__device__ int   g_bsum[256];
__device__ int   g_boff[256];
__device__ float g_dinv[NMAX];
__device__ alignas(16) __half g_hs16[(size_t)NMAX * NHID];  // fp16 hs (gather src)
__device__ alignas(16) float  g_accA[(size_t)NMAX * NHID];
__device__ alignas(16) float  g_accB[(size_t)NMAX * NHID];
__device__ float g_gsum[NGRAPH * NHID];
__device__ int   g_gcnt[NGRAPH];

union H8I4 { int4 i; __half2 h[4]; };
union H4U2 { uint2 u; __half2 h[2]; };
union H2U  { unsigned u; __half2 h; };

__device__ __forceinline__ unsigned smem_u32(const void* p) {
    unsigned r;
    asm("{ .reg .u64 t; cvta.to.shared.u64 t, %1; cvt.u32.u64 %0, t; }"
        : "=r"(r) : "l"(p));
    return r;
}

// ---------------------------------------------------------------------------
__global__ void k_init(int N) {
    int i = blockIdx.x * blockDim.x + threadIdx.x;
    if (i < N) g_ecnt[i] = 0;
    if (i < NGRAPH * NHID) g_gsum[i] = 0.f;
    if (i < NGRAPH) g_gcnt[i] = 0;
}

__global__ void k_edge_prep(const int* __restrict__ ei, int E, int N) {
    int e = blockIdx.x * blockDim.x + threadIdx.x;
    if (e >= E) return;
    int s = ei[e];
    int d = ei[E + e];
    if ((unsigned)s >= (unsigned)N || (unsigned)d >= (unsigned)N) return;
    atomicAdd(&g_ecnt[d], 1);
}

// ---- 3-kernel exclusive scan of g_ecnt -> g_off -------------------------
__device__ __forceinline__ int block_incl_scan(int v, int tid) {
    __shared__ int wsum[16];
    int lane = tid & 31, w = tid >> 5;
    int x = v;
#pragma unroll
    for (int o = 1; o < 32; o <<= 1) {
        int t = __shfl_up_sync(0xffffffffu, x, o);
        if (lane >= o) x += t;
    }
    if (lane == 31) wsum[w] = x;
    __syncthreads();
    if (w == 0) {
        int y = (lane < (blockDim.x >> 5)) ? wsum[lane] : 0;
#pragma unroll
        for (int o = 1; o < 16; o <<= 1) {
            int t = __shfl_up_sync(0xffffffffu, y, o);
            if (lane >= o) y += t;
        }
        if (lane < 16) wsum[lane] = y;
    }
    __syncthreads();
    return x + (w > 0 ? wsum[w - 1] : 0);
}

__global__ void k_scanA(int N) {
    int i = blockIdx.x * SCAN_B + threadIdx.x;
    int v = (i < N) ? g_ecnt[i] : 0;
    int incl = block_incl_scan(v, threadIdx.x);
    if (i < N) g_scan[i] = incl - v;
    if (threadIdx.x == SCAN_B - 1) g_bsum[blockIdx.x] = incl;
}

__global__ void k_scanB(int nb) {
    int t = threadIdx.x;
    int v = (t < nb) ? g_bsum[t] : 0;
    int incl = block_incl_scan(v, t);
    if (t < 256) g_boff[t] = incl - v;
}

__global__ void k_scanC(int N) {
    int i = blockIdx.x * SCAN_B + threadIdx.x;
    if (i >= N) return;
    int off = g_scan[i] + g_boff[blockIdx.x];
    g_off[i] = off;
    g_cursor[i] = off;
    g_dinv[i] = rsqrtf((float)(g_ecnt[i] + 1));   // +1 self-loop
}

__global__ void k_csr_fill(const int* __restrict__ ei, int E, int N) {
    int e = blockIdx.x * blockDim.x + threadIdx.x;
    if (e >= E) return;
    int s = ei[e];
    int d = ei[E + e];
    if ((unsigned)s >= (unsigned)N || (unsigned)d >= (unsigned)N) return;
    int pos = atomicAdd(&g_cursor[d], 1);
    g_csrc[pos] = s;
}

// ---------------------------------------------------------------------------
// Layer 1 GEMM via HMMA (m16n8k16, fp16 in / fp32 acc):
//   hs16[n] = fp16(dinv[n] * (x[n] @ W1)).
// 128 threads = 4 warps; 64 nodes x 64 cols per block; K = 128.
#define XS_LD 136   // 128 + 8 halves
#define WS_LD 72    // 64 + 8 halves
__global__ void k_gemm1(const float* __restrict__ x, const float* __restrict__ W, int N) {
    __shared__ __half xs[64 * XS_LD];    // 17408 B
    __shared__ __half ws[NFEAT * WS_LD]; // 18432 B
    int tid = threadIdx.x;
    int nb = blockIdx.x * 64;
    const float4* x4 = reinterpret_cast<const float4*>(x);
    const float4* W4 = reinterpret_cast<const float4*>(W);

    // W1 [128][64] -> ws fp16
    for (int i = tid; i < NFEAT * 16; i += 128) {
        int k = i >> 4, c4 = i & 15;
        float4 v = W4[i];
        H4U2 u;
        u.h[0] = __floats2half2_rn(v.x, v.y);
        u.h[1] = __floats2half2_rn(v.z, v.w);
        *reinterpret_cast<uint2*>(&ws[k * WS_LD + c4 * 4]) = u.u;
    }
    // x tile [64][128] -> xs fp16
    for (int i = tid; i < 64 * 32; i += 128) {
        int n = i >> 5, c4 = i & 31;
        float4 v = (nb + n < N) ? x4[(size_t)(nb + n) * 32 + c4]
                                : make_float4(0.f, 0.f, 0.f, 0.f);
        H4U2 u;
        u.h[0] = __floats2half2_rn(v.x, v.y);
        u.h[1] = __floats2half2_rn(v.z, v.w);
        *reinterpret_cast<uint2*>(&xs[n * XS_LD + c4 * 4]) = u.u;
    }
    __syncthreads();

    int lane = tid & 31, warp = tid >> 5;
    int m0 = warp * 16;
    int g = lane >> 2, t = lane & 3;
    float c[8][4];
#pragma unroll
    for (int nt = 0; nt < 8; nt++)
#pragma unroll
        for (int r = 0; r < 4; r++) c[nt][r] = 0.f;

    unsigned xs_base = smem_u32(xs);
    unsigned ws_base = smem_u32(ws);
    int aRow = m0 + (lane & 15);
    int aHalf = lane >> 4;

#pragma unroll
    for (int ks = 0; ks < 8; ks++) {
        unsigned aAddr = xs_base + (unsigned)((aRow * XS_LD + ks * 16 + aHalf * 8) * 2);
        unsigned a0, a1, a2, a3;
        asm volatile("ldmatrix.sync.aligned.m8n8.x4.shared.b16 {%0,%1,%2,%3}, [%4];"
                     : "=r"(a0), "=r"(a1), "=r"(a2), "=r"(a3) : "r"(aAddr));
        int bRow = ks * 16 + (lane & 15);
#pragma unroll
        for (int nt = 0; nt < 8; nt++) {
            unsigned bAddr = ws_base + (unsigned)((bRow * WS_LD + nt * 8) * 2);
            unsigned b0, b1;
            asm volatile("ldmatrix.sync.aligned.m8n8.x2.trans.shared.b16 {%0,%1}, [%2];"
                         : "=r"(b0), "=r"(b1) : "r"(bAddr));
            asm volatile(
                "mma.sync.aligned.m16n8k16.row.col.f32.f16.f16.f32 "
                "{%0,%1,%2,%3}, {%4,%5,%6,%7}, {%8,%9}, {%0,%1,%2,%3};"
                : "+f"(c[nt][0]), "+f"(c[nt][1]), "+f"(c[nt][2]), "+f"(c[nt][3])
                : "r"(a0), "r"(a1), "r"(a2), "r"(a3), "r"(b0), "r"(b1));
        }
    }

    int row0 = nb + m0 + g;
    int row1 = row0 + 8;
    float dv0 = (row0 < N) ? g_dinv[row0] : 0.f;
    float dv1 = (row1 < N) ? g_dinv[row1] : 0.f;
    unsigned* hsu = reinterpret_cast<unsigned*>(g_hs16);
#pragma unroll
    for (int nt = 0; nt < 8; nt++) {
        if (row0 < N) {
            H2U u; u.h = __floats2half2_rn(c[nt][0] * dv0, c[nt][1] * dv0);
            hsu[(size_t)row0 * 32 + nt * 4 + t] = u.u;
        }
        if (row1 < N) {
            H2U u; u.h = __floats2half2_rn(c[nt][2] * dv1, c[nt][3] * dv1);
            hsu[(size_t)row1 * 32 + nt * 4 + t] = u.u;
        }
    }
}

// ---------------------------------------------------------------------------
// Layers 2/3 GEMM via HMMA (K = 64): in = relu(dinv*accPrev + bPrev) rounded
// to fp16 during smem staging; hs16 = fp16(dinv * (in @ W)).
#define XS2_LD 72   // 64 + 8 halves
__global__ void k_gemm23(const float* __restrict__ accPrev, const float* __restrict__ bPrev,
                         const float* __restrict__ W, int N) {
    __shared__ __half xs[64 * XS2_LD];   // 9216 B
    __shared__ __half ws[NHID * WS_LD];  // 9216 B
    int tid = threadIdx.x;
    int nb = blockIdx.x * 64;
    const float4* W4 = reinterpret_cast<const float4*>(W);
    const float4* acc4 = reinterpret_cast<const float4*>(accPrev);
    const float4* b4p = reinterpret_cast<const float4*>(bPrev);

    // W [64][64] -> ws fp16
    for (int i = tid; i < NHID * 16; i += 128) {
        int k = i >> 4, c4 = i & 15;
        float4 v = W4[i];
        H4U2 u;
        u.h[0] = __floats2half2_rn(v.x, v.y);
        u.h[1] = __floats2half2_rn(v.z, v.w);
        *reinterpret_cast<uint2*>(&ws[k * WS_LD + c4 * 4]) = u.u;
    }
    // in tile [64][64]: relu(dinv*acc + b) -> xs fp16
    for (int i = tid; i < 64 * 16; i += 128) {
        int n = i >> 4, k4 = i & 15;
        float4 o = make_float4(0.f, 0.f, 0.f, 0.f);
        if (nb + n < N) {
            float4 av = acc4[(size_t)(nb + n) * 16 + k4];
            float4 bb = b4p[k4];
            float dv = g_dinv[nb + n];
            o.x = fmaxf(fmaf(dv, av.x, bb.x), 0.f);
            o.y = fmaxf(fmaf(dv, av.y, bb.y), 0.f);
            o.z = fmaxf(fmaf(dv, av.z, bb.z), 0.f);
            o.w = fmaxf(fmaf(dv, av.w, bb.w), 0.f);
        }
        H4U2 u;
        u.h[0] = __floats2half2_rn(o.x, o.y);
        u.h[1] = __floats2half2_rn(o.z, o.w);
        *reinterpret_cast<uint2*>(&xs[n * XS2_LD + k4 * 4]) = u.u;
    }
    __syncthreads();

    int lane = tid & 31, warp = tid >> 5;
    int m0 = warp * 16;
    int g = lane >> 2, t = lane & 3;
    float c[8][4];
#pragma unroll
    for (int nt = 0; nt < 8; nt++)
#pragma unroll
        for (int r = 0; r < 4; r++) c[nt][r] = 0.f;

    unsigned xs_base = smem_u32(xs);
    unsigned ws_base = smem_u32(ws);
    int aRow = m0 + (lane & 15);
    int aHalf = lane >> 4;

#pragma unroll
    for (int ks = 0; ks < 4; ks++) {
        unsigned aAddr = xs_base + (unsigned)((aRow * XS2_LD + ks * 16 + aHalf * 8) * 2);
        unsigned a0, a1, a2, a3;
        asm volatile("ldmatrix.sync.aligned.m8n8.x4.shared.b16 {%0,%1,%2,%3}, [%4];"
                     : "=r"(a0), "=r"(a1), "=r"(a2), "=r"(a3) : "r"(aAddr));
        int bRow = ks * 16 + (lane & 15);
#pragma unroll
        for (int nt = 0; nt < 8; nt++) {
            unsigned bAddr = ws_base + (unsigned)((bRow * WS_LD + nt * 8) * 2);
            unsigned b0, b1;
            asm volatile("ldmatrix.sync.aligned.m8n8.x2.trans.shared.b16 {%0,%1}, [%2];"
                         : "=r"(b0), "=r"(b1) : "r"(bAddr));
            asm volatile(
                "mma.sync.aligned.m16n8k16.row.col.f32.f16.f16.f32 "
                "{%0,%1,%2,%3}, {%4,%5,%6,%7}, {%8,%9}, {%0,%1,%2,%3};"
                : "+f"(c[nt][0]), "+f"(c[nt][1]), "+f"(c[nt][2]), "+f"(c[nt][3])
                : "r"(a0), "r"(a1), "r"(a2), "r"(a3), "r"(b0), "r"(b1));
        }
    }

    int row0 = nb + m0 + g;
    int row1 = row0 + 8;
    float dv0 = (row0 < N) ? g_dinv[row0] : 0.f;
    float dv1 = (row1 < N) ? g_dinv[row1] : 0.f;
    unsigned* hsu = reinterpret_cast<unsigned*>(g_hs16);
#pragma unroll
    for (int nt = 0; nt < 8; nt++) {
        if (row0 < N) {
            H2U u; u.h = __floats2half2_rn(c[nt][0] * dv0, c[nt][1] * dv0);
            hsu[(size_t)row0 * 32 + nt * 4 + t] = u.u;
        }
        if (row1 < N) {
            H2U u; u.h = __floats2half2_rn(c[nt][2] * dv1, c[nt][3] * dv1);
            hsu[(size_t)row1 * 32 + nt * 4 + t] = u.u;
        }
    }
}

// ---------------------------------------------------------------------------
// CSR gather aggregation (fp16 source, HADD2 slot accumulate, fp32 reduce):
// acc[n] = hs[n] (self-loop) + sum_{s in in(n)} hs[s].
__global__ void k_agg(float* __restrict__ accOut, int N) {
    int warp = (blockIdx.x * blockDim.x + threadIdx.x) >> 5;
    if (warp >= N) return;
    int lane = threadIdx.x & 31;
    int p = lane & 7;        // 16B chunk (cols p*8 .. p*8+7)
    int q = lane >> 3;       // edge slot 0..3
    const int4* h16 = reinterpret_cast<const int4*>(g_hs16);
    const int* __restrict__ csrc = g_csrc;
    int n = warp;
    int start = g_off[n];
    int end = start + g_ecnt[n];

    __half2 a[4];
    if (q == 0) {            // self-loop init
        H8I4 v; v.i = h16[(size_t)n * 8 + p];
#pragma unroll
        for (int i = 0; i < 4; i++) a[i] = v.h[i];
    } else {
#pragma unroll
        for (int i = 0; i < 4; i++) a[i] = __half2half2(__ushort_as_half(0));
    }
    int j = start + q;
    for (; j + 4 < end; j += 8) {
        int sA = csrc[j];
        int sB = csrc[j + 4];
        H8I4 vA; vA.i = h16[(size_t)sA * 8 + p];
        H8I4 vB; vB.i = h16[(size_t)sB * 8 + p];
#pragma unroll
        for (int i = 0; i < 4; i++) a[i] = __hadd2(a[i], vA.h[i]);
#pragma unroll
        for (int i = 0; i < 4; i++) a[i] = __hadd2(a[i], vB.h[i]);
    }
    if (j < end) {
        int s = csrc[j];
        H8I4 v; v.i = h16[(size_t)s * 8 + p];
#pragma unroll
        for (int i = 0; i < 4; i++) a[i] = __hadd2(a[i], v.h[i]);
    }
    float f[8];
#pragma unroll
    for (int i = 0; i < 4; i++) {
        float2 t = __half22float2(a[i]);
        f[2 * i] = t.x; f[2 * i + 1] = t.y;
    }
    const unsigned F = 0xffffffffu;
#pragma unroll
    for (int off = 8; off <= 16; off <<= 1) {
#pragma unroll
        for (int i = 0; i < 8; i++) f[i] += __shfl_xor_sync(F, f[i], off);
    }
    if (lane < 8) {
        float4* out4 = reinterpret_cast<float4*>(accOut);
        out4[(size_t)n * 16 + lane * 2]     = make_float4(f[0], f[1], f[2], f[3]);
        out4[(size_t)n * 16 + lane * 2 + 1] = make_float4(f[4], f[5], f[6], f[7]);
    }
}

// ---------------------------------------------------------------------------
__global__ void k_pool(const float* __restrict__ acc3, const float* __restrict__ b3,
                       const int* __restrict__ batch, int N) {
    int t = blockIdx.x * blockDim.x + threadIdx.x;
    int c = t & 63;
    int n0 = (t >> 6) * 4;
    if (n0 >= N) return;
    float b = b3[c];
    float accum = 0.f;
    int cnt = 0;
    int gprev = -1;
    for (int j = 0; j < 4; j++) {
        int n = n0 + j;
        if (n >= N) break;
        int g = batch[n];
        if ((unsigned)g >= NGRAPH) continue;
        if (g != gprev) {
            if (gprev >= 0) {
                atomicAdd(&g_gsum[gprev * NHID + c], accum);
                if (c == 0) atomicAdd(&g_gcnt[gprev], cnt);
            }
            accum = 0.f; cnt = 0; gprev = g;
        }
        accum += fmaxf(fmaf(g_dinv[n], acc3[(size_t)n * NHID + c], b), 0.f);
        cnt++;
    }
    if (gprev >= 0) {
        atomicAdd(&g_gsum[gprev * NHID + c], accum);
        if (c == 0) atomicAdd(&g_gcnt[gprev], cnt);
    }
}

__global__ void k_head(const float* __restrict__ Wl, const float* __restrict__ bl,
                       float* __restrict__ out) {
    int g = threadIdx.x;
    if (g >= NGRAPH) return;
    float cnt = fmaxf((float)g_gcnt[g], 1.f);
    float inv = 1.f / cnt;
    float l[NCLASS];
#pragma unroll
    for (int c = 0; c < NCLASS; c++) l[c] = bl[c];
    for (int k = 0; k < NHID; k++) {
        float p = g_gsum[g * NHID + k] * inv;
#pragma unroll
        for (int c = 0; c < NCLASS; c++) l[c] = fmaf(p, Wl[k * NCLASS + c], l[c]);
    }
    float m = l[0];
#pragma unroll
    for (int c = 1; c < NCLASS; c++) m = fmaxf(m, l[c]);
    float s = 0.f;
#pragma unroll
    for (int c = 0; c < NCLASS; c++) { l[c] = __expf(l[c] - m); s += l[c]; }
    float is = 1.f / s;
#pragma unroll
    for (int c = 0; c < NCLASS; c++) out[g * NCLASS + c] = l[c] * is;
}

// ---------------------------------------------------------------------------
extern "C" void kernel_launch(void* const* d_in, const int* in_sizes, int n_in,
                              void* d_out, int out_size) {
    const float* x     = (const float*)d_in[0];
    const int*   ei    = (const int*)d_in[1];
    const int*   batch = (const int*)d_in[2];
    const float* W1 = (const float*)d_in[3];
    const float* b1 = (const float*)d_in[4];
    const float* W2 = (const float*)d_in[5];
    const float* b2 = (const float*)d_in[6];
    const float* W3 = (const float*)d_in[7];
    const float* b3 = (const float*)d_in[8];
    const float* Wl = (const float*)d_in[9];
    const float* bl = (const float*)d_in[10];
    float* out = (float*)d_out;

    int N = in_sizes[0] / NFEAT;
    int E = in_sizes[1] / 2;

    float *accA = nullptr, *accB = nullptr;
    cudaGetSymbolAddress((void**)&accA, g_accA);
    cudaGetSymbolAddress((void**)&accB, g_accB);

    const int T = 256;
    int nScanBlocks = (N + SCAN_B - 1) / SCAN_B;

    k_init<<<(N + T - 1) / T, T>>>(N);
    k_edge_prep<<<(E + T - 1) / T, T>>>(ei, E, N);
    k_scanA<<<nScanBlocks, SCAN_B>>>(N);
    k_scanB<<<1, 256>>>(nScanBlocks);
    k_scanC<<<nScanBlocks, SCAN_B>>>(N);
    k_csr_fill<<<(E + T - 1) / T, T>>>(ei, E, N);

    int gemm1Blocks = (N + 63) / 64;
    int aggBlocks = (N * 32 + T - 1) / T;

    // Layer 1 (HMMA, K=128)
    k_gemm1<<<gemm1Blocks, 128>>>(x, W1, N);
    k_agg<<<aggBlocks, T>>>(accA, N);
    // Layer 2 (HMMA, K=64)
    k_gemm23<<<gemm1Blocks, 128>>>(accA, b1, W2, N);
    k_agg<<<aggBlocks, T>>>(accB, N);
    // Layer 3 (HMMA, K=64)
    k_gemm23<<<gemm1Blocks, 128>>>(accB, b2, W3, N);
    k_agg<<<aggBlocks, T>>>(accA, N);

    // Pool + head
    k_pool<<<(((N + 3) / 4) * 64 + T - 1) / T, T>>>(accA, b3, batch, N);
    k_head<<<1, 64>>>(Wl, bl, out);
}

// round 13
// speedup vs baseline: 1.3667x; 1.0701x over previous
#include <cuda_runtime.h>
#include <cuda_fp16.h>

#define NMAX   100000
#define EMAX   1600000
#define NGRAPH 64
#define NFEAT  128
#define NHID   64
#define NCLASS 10
#define SCAN_B 512

// ---- scratch (allocation-free rule: __device__ globals) ----
__device__ int   g_csrc[EMAX];          // CSR: src ids grouped by dst
__device__ int   g_ecnt[NMAX];          // in-degree (edges only); reset by scanC
__device__ int   g_off[NMAX + 1];       // CSR row offsets (+ sentinel)
__device__ int   g_cursor[NMAX];
__device__ int   g_scan[NMAX];
__device__ int   g_bsum[256];
__device__ int   g_boff[256];
__device__ float g_dinv[NMAX];
__device__ alignas(16) __half g_hs16[(size_t)NMAX * NHID];  // gemm out (gather src)
__device__ alignas(16) __half g_in16[(size_t)NMAX * NHID];  // agg out  (gemm in)
__device__ float g_gsum[NGRAPH * NHID];
__device__ int   g_gcnt[NGRAPH];

union H8I4 { int4 i; __half2 h[4]; };
union H4U2 { uint2 u; __half2 h[2]; };
union H2U  { unsigned u; __half2 h; };

__device__ __forceinline__ unsigned smem_u32(const void* p) {
    unsigned r;
    asm("{ .reg .u64 t; cvta.to.shared.u64 t, %1; cvt.u32.u64 %0, t; }"
        : "=r"(r) : "l"(p));
    return r;
}

// ---------------------------------------------------------------------------
__global__ void k_edge_prep(const int* __restrict__ ei, int E, int N) {
    int e = blockIdx.x * blockDim.x + threadIdx.x;
    if (e >= E) return;
    int s = ei[e];
    int d = ei[E + e];
    if ((unsigned)s >= (unsigned)N || (unsigned)d >= (unsigned)N) return;
    atomicAdd(&g_ecnt[d], 1);
}

// ---- 3-kernel exclusive scan of g_ecnt -> g_off -------------------------
__device__ __forceinline__ int block_incl_scan(int v, int tid) {
    __shared__ int wsum[16];
    int lane = tid & 31, w = tid >> 5;
    int x = v;
#pragma unroll
    for (int o = 1; o < 32; o <<= 1) {
        int t = __shfl_up_sync(0xffffffffu, x, o);
        if (lane >= o) x += t;
    }
    if (lane == 31) wsum[w] = x;
    __syncthreads();
    if (w == 0) {
        int y = (lane < (blockDim.x >> 5)) ? wsum[lane] : 0;
#pragma unroll
        for (int o = 1; o < 16; o <<= 1) {
            int t = __shfl_up_sync(0xffffffffu, y, o);
            if (lane >= o) y += t;
        }
        if (lane < 16) wsum[lane] = y;
    }
    __syncthreads();
    return x + (w > 0 ? wsum[w - 1] : 0);
}

__global__ void k_scanA(int N) {
    int i = blockIdx.x * SCAN_B + threadIdx.x;
    int v = (i < N) ? g_ecnt[i] : 0;
    int incl = block_incl_scan(v, threadIdx.x);
    if (i < N) g_scan[i] = incl - v;
    if (threadIdx.x == SCAN_B - 1) g_bsum[blockIdx.x] = incl;
}

// scanB also zeroes the pool accumulators (was k_init).
__global__ void k_scanB(int nb) {
    int t = threadIdx.x;
    int v = (t < nb) ? g_bsum[t] : 0;
    int incl = block_incl_scan(v, t);
    if (t < 256) g_boff[t] = incl - v;
    for (int i = t; i < NGRAPH * NHID; i += 256) g_gsum[i] = 0.f;
    if (t < NGRAPH) g_gcnt[t] = 0;
}

// scanC: offsets + dinv + sentinel; resets ecnt for the next graph replay.
__global__ void k_scanC(int N) {
    int i = blockIdx.x * SCAN_B + threadIdx.x;
    if (i >= N) return;
    int off = g_scan[i] + g_boff[blockIdx.x];
    int cnt = g_ecnt[i];
    g_off[i] = off;
    g_cursor[i] = off;
    g_dinv[i] = rsqrtf((float)(cnt + 1));   // +1 self-loop
    g_ecnt[i] = 0;                          // reset for next run
    if (i == N - 1) g_off[N] = off + cnt;
}

__global__ void k_csr_fill(const int* __restrict__ ei, int E, int N) {
    int e = blockIdx.x * blockDim.x + threadIdx.x;
    if (e >= E) return;
    int s = ei[e];
    int d = ei[E + e];
    if ((unsigned)s >= (unsigned)N || (unsigned)d >= (unsigned)N) return;
    int pos = atomicAdd(&g_cursor[d], 1);
    g_csrc[pos] = s;
}

// ---------------------------------------------------------------------------
// Layer 1 GEMM via HMMA (m16n8k16, fp16 in / fp32 acc):
//   hs16[n] = fp16(dinv[n] * (x[n] @ W1)).
#define XS_LD 136   // 128 + 8 halves
#define WS_LD 72    // 64 + 8 halves
__global__ void k_gemm1(const float* __restrict__ x, const float* __restrict__ W, int N) {
    __shared__ __half xs[64 * XS_LD];    // 17408 B
    __shared__ __half ws[NFEAT * WS_LD]; // 18432 B
    int tid = threadIdx.x;
    int nb = blockIdx.x * 64;
    const float4* x4 = reinterpret_cast<const float4*>(x);
    const float4* W4 = reinterpret_cast<const float4*>(W);

    for (int i = tid; i < NFEAT * 16; i += 128) {
        int k = i >> 4, c4 = i & 15;
        float4 v = W4[i];
        H4U2 u;
        u.h[0] = __floats2half2_rn(v.x, v.y);
        u.h[1] = __floats2half2_rn(v.z, v.w);
        *reinterpret_cast<uint2*>(&ws[k * WS_LD + c4 * 4]) = u.u;
    }
    for (int i = tid; i < 64 * 32; i += 128) {
        int n = i >> 5, c4 = i & 31;
        float4 v = (nb + n < N) ? x4[(size_t)(nb + n) * 32 + c4]
                                : make_float4(0.f, 0.f, 0.f, 0.f);
        H4U2 u;
        u.h[0] = __floats2half2_rn(v.x, v.y);
        u.h[1] = __floats2half2_rn(v.z, v.w);
        *reinterpret_cast<uint2*>(&xs[n * XS_LD + c4 * 4]) = u.u;
    }
    __syncthreads();

    int lane = tid & 31, warp = tid >> 5;
    int m0 = warp * 16;
    int g = lane >> 2, t = lane & 3;
    float c[8][4];
#pragma unroll
    for (int nt = 0; nt < 8; nt++)
#pragma unroll
        for (int r = 0; r < 4; r++) c[nt][r] = 0.f;

    unsigned xs_base = smem_u32(xs);
    unsigned ws_base = smem_u32(ws);
    int aRow = m0 + (lane & 15);
    int aHalf = lane >> 4;

#pragma unroll
    for (int ks = 0; ks < 8; ks++) {
        unsigned aAddr = xs_base + (unsigned)((aRow * XS_LD + ks * 16 + aHalf * 8) * 2);
        unsigned a0, a1, a2, a3;
        asm volatile("ldmatrix.sync.aligned.m8n8.x4.shared.b16 {%0,%1,%2,%3}, [%4];"
                     : "=r"(a0), "=r"(a1), "=r"(a2), "=r"(a3) : "r"(aAddr));
        int bRow = ks * 16 + (lane & 15);
#pragma unroll
        for (int nt = 0; nt < 8; nt++) {
            unsigned bAddr = ws_base + (unsigned)((bRow * WS_LD + nt * 8) * 2);
            unsigned b0, b1;
            asm volatile("ldmatrix.sync.aligned.m8n8.x2.trans.shared.b16 {%0,%1}, [%2];"
                         : "=r"(b0), "=r"(b1) : "r"(bAddr));
            asm volatile(
                "mma.sync.aligned.m16n8k16.row.col.f32.f16.f16.f32 "
                "{%0,%1,%2,%3}, {%4,%5,%6,%7}, {%8,%9}, {%0,%1,%2,%3};"
                : "+f"(c[nt][0]), "+f"(c[nt][1]), "+f"(c[nt][2]), "+f"(c[nt][3])
                : "r"(a0), "r"(a1), "r"(a2), "r"(a3), "r"(b0), "r"(b1));
        }
    }

    int row0 = nb + m0 + g;
    int row1 = row0 + 8;
    float dv0 = (row0 < N) ? g_dinv[row0] : 0.f;
    float dv1 = (row1 < N) ? g_dinv[row1] : 0.f;
    unsigned* hsu = reinterpret_cast<unsigned*>(g_hs16);
#pragma unroll
    for (int nt = 0; nt < 8; nt++) {
        if (row0 < N) {
            H2U u; u.h = __floats2half2_rn(c[nt][0] * dv0, c[nt][1] * dv0);
            hsu[(size_t)row0 * 32 + nt * 4 + t] = u.u;
        }
        if (row1 < N) {
            H2U u; u.h = __floats2half2_rn(c[nt][2] * dv1, c[nt][3] * dv1);
            hsu[(size_t)row1 * 32 + nt * 4 + t] = u.u;
        }
    }
}

// ---------------------------------------------------------------------------
// Layers 2/3 GEMM via HMMA (K = 64): input = g_in16 (already relu'd fp16);
// hs16 = fp16(dinv * (in @ W)).
#define XS2_LD 72   // 64 + 8 halves
__global__ void k_gemm23(const float* __restrict__ W, int N) {
    __shared__ __half xs[64 * XS2_LD];   // 9216 B
    __shared__ __half ws[NHID * WS_LD];  // 9216 B
    int tid = threadIdx.x;
    int nb = blockIdx.x * 64;
    const float4* W4 = reinterpret_cast<const float4*>(W);
    const int4* in4 = reinterpret_cast<const int4*>(g_in16);

    for (int i = tid; i < NHID * 16; i += 128) {
        int k = i >> 4, c4 = i & 15;
        float4 v = W4[i];
        H4U2 u;
        u.h[0] = __floats2half2_rn(v.x, v.y);
        u.h[1] = __floats2half2_rn(v.z, v.w);
        *reinterpret_cast<uint2*>(&ws[k * WS_LD + c4 * 4]) = u.u;
    }
    // in tile [64][64] fp16: raw int4 copy (8 halves per iteration)
    for (int i = tid; i < 64 * 8; i += 128) {
        int n = i >> 3, c8 = i & 7;
        int4 v = (nb + n < N) ? in4[(size_t)(nb + n) * 8 + c8]
                              : make_int4(0, 0, 0, 0);
        *reinterpret_cast<int4*>(&xs[n * XS2_LD + c8 * 8]) = v;
    }
    __syncthreads();

    int lane = tid & 31, warp = tid >> 5;
    int m0 = warp * 16;
    int g = lane >> 2, t = lane & 3;
    float c[8][4];
#pragma unroll
    for (int nt = 0; nt < 8; nt++)
#pragma unroll
        for (int r = 0; r < 4; r++) c[nt][r] = 0.f;

    unsigned xs_base = smem_u32(xs);
    unsigned ws_base = smem_u32(ws);
    int aRow = m0 + (lane & 15);
    int aHalf = lane >> 4;

#pragma unroll
    for (int ks = 0; ks < 4; ks++) {
        unsigned aAddr = xs_base + (unsigned)((aRow * XS2_LD + ks * 16 + aHalf * 8) * 2);
        unsigned a0, a1, a2, a3;
        asm volatile("ldmatrix.sync.aligned.m8n8.x4.shared.b16 {%0,%1,%2,%3}, [%4];"
                     : "=r"(a0), "=r"(a1), "=r"(a2), "=r"(a3) : "r"(aAddr));
        int bRow = ks * 16 + (lane & 15);
#pragma unroll
        for (int nt = 0; nt < 8; nt++) {
            unsigned bAddr = ws_base + (unsigned)((bRow * WS_LD + nt * 8) * 2);
            unsigned b0, b1;
            asm volatile("ldmatrix.sync.aligned.m8n8.x2.trans.shared.b16 {%0,%1}, [%2];"
                         : "=r"(b0), "=r"(b1) : "r"(bAddr));
            asm volatile(
                "mma.sync.aligned.m16n8k16.row.col.f32.f16.f16.f32 "
                "{%0,%1,%2,%3}, {%4,%5,%6,%7}, {%8,%9}, {%0,%1,%2,%3};"
                : "+f"(c[nt][0]), "+f"(c[nt][1]), "+f"(c[nt][2]), "+f"(c[nt][3])
                : "r"(a0), "r"(a1), "r"(a2), "r"(a3), "r"(b0), "r"(b1));
        }
    }

    int row0 = nb + m0 + g;
    int row1 = row0 + 8;
    float dv0 = (row0 < N) ? g_dinv[row0] : 0.f;
    float dv1 = (row1 < N) ? g_dinv[row1] : 0.f;
    unsigned* hsu = reinterpret_cast<unsigned*>(g_hs16);
#pragma unroll
    for (int nt = 0; nt < 8; nt++) {
        if (row0 < N) {
            H2U u; u.h = __floats2half2_rn(c[nt][0] * dv0, c[nt][1] * dv0);
            hsu[(size_t)row0 * 32 + nt * 4 + t] = u.u;
        }
        if (row1 < N) {
            H2U u; u.h = __floats2half2_rn(c[nt][2] * dv1, c[nt][3] * dv1);
            hsu[(size_t)row1 * 32 + nt * 4 + t] = u.u;
        }
    }
}

// ---------------------------------------------------------------------------
// CSR gather aggregation + fused next-layer input transform:
//   sum = hs[n] + sum_{s in in(n)} hs[s]   (fp16 HADD2 slots, fp32 reduce)
//   in16[n][c] = fp16(relu(dinv[n]*sum[c] + bias[c]))
__global__ void k_agg(const float* __restrict__ bias, int N) {
    int warp = (blockIdx.x * blockDim.x + threadIdx.x) >> 5;
    if (warp >= N) return;
    int lane = threadIdx.x & 31;
    int p = lane & 7;        // 16B chunk (cols p*8 .. p*8+7)
    int q = lane >> 3;       // edge slot 0..3
    const int4* h16 = reinterpret_cast<const int4*>(g_hs16);
    const int* __restrict__ csrc = g_csrc;
    int n = warp;
    int start = g_off[n];
    int end = g_off[n + 1];

    __half2 a[4];
    if (q == 0) {            // self-loop init
        H8I4 v; v.i = h16[(size_t)n * 8 + p];
#pragma unroll
        for (int i = 0; i < 4; i++) a[i] = v.h[i];
    } else {
#pragma unroll
        for (int i = 0; i < 4; i++) a[i] = __half2half2(__ushort_as_half(0));
    }
    int j = start + q;
    for (; j + 4 < end; j += 8) {
        int sA = csrc[j];
        int sB = csrc[j + 4];
        H8I4 vA; vA.i = h16[(size_t)sA * 8 + p];
        H8I4 vB; vB.i = h16[(size_t)sB * 8 + p];
#pragma unroll
        for (int i = 0; i < 4; i++) a[i] = __hadd2(a[i], vA.h[i]);
#pragma unroll
        for (int i = 0; i < 4; i++) a[i] = __hadd2(a[i], vB.h[i]);
    }
    if (j < end) {
        int s = csrc[j];
        H8I4 v; v.i = h16[(size_t)s * 8 + p];
#pragma unroll
        for (int i = 0; i < 4; i++) a[i] = __hadd2(a[i], v.h[i]);
    }
    float f[8];
#pragma unroll
    for (int i = 0; i < 4; i++) {
        float2 t = __half22float2(a[i]);
        f[2 * i] = t.x; f[2 * i + 1] = t.y;
    }
    const unsigned F = 0xffffffffu;
#pragma unroll
    for (int off = 8; off <= 16; off <<= 1) {
#pragma unroll
        for (int i = 0; i < 8; i++) f[i] += __shfl_xor_sync(F, f[i], off);
    }
    if (lane < 8) {
        // fused epilogue: relu(dinv*sum + b) -> fp16
        const float4* b4 = reinterpret_cast<const float4*>(bias);
        float4 bb0 = b4[lane * 2];
        float4 bb1 = b4[lane * 2 + 1];
        float dv = g_dinv[n];
        float v0 = fmaxf(fmaf(dv, f[0], bb0.x), 0.f);
        float v1 = fmaxf(fmaf(dv, f[1], bb0.y), 0.f);
        float v2 = fmaxf(fmaf(dv, f[2], bb0.z), 0.f);
        float v3 = fmaxf(fmaf(dv, f[3], bb0.w), 0.f);
        float v4 = fmaxf(fmaf(dv, f[4], bb1.x), 0.f);
        float v5 = fmaxf(fmaf(dv, f[5], bb1.y), 0.f);
        float v6 = fmaxf(fmaf(dv, f[6], bb1.z), 0.f);
        float v7 = fmaxf(fmaf(dv, f[7], bb1.w), 0.f);
        H8I4 o;
        o.h[0] = __floats2half2_rn(v0, v1);
        o.h[1] = __floats2half2_rn(v2, v3);
        o.h[2] = __floats2half2_rn(v4, v5);
        o.h[3] = __floats2half2_rn(v6, v7);
        reinterpret_cast<int4*>(g_in16)[(size_t)n * 8 + lane] = o.i;
    }
}

// ---------------------------------------------------------------------------
// Pool: segment-sum of g_in16 (already relu'd); 4-node run-length batching.
// Thread handles one half2 column pair (c2) and 4 consecutive nodes.
__global__ void k_pool(const int* __restrict__ batch, int N) {
    int t = blockIdx.x * blockDim.x + threadIdx.x;
    int c2 = t & 31;              // half2 col index (cols 2*c2, 2*c2+1)
    int n0 = (t >> 5) * 4;
    if (n0 >= N) return;
    const __half2* in2 = reinterpret_cast<const __half2*>(g_in16);
    float ax = 0.f, ay = 0.f;
    int cnt = 0;
    int gprev = -1;
    for (int j = 0; j < 4; j++) {
        int n = n0 + j;
        if (n >= N) break;
        int g = batch[n];
        if ((unsigned)g >= NGRAPH) continue;
        if (g != gprev) {
            if (gprev >= 0) {
                atomicAdd(&g_gsum[gprev * NHID + c2 * 2], ax);
                atomicAdd(&g_gsum[gprev * NHID + c2 * 2 + 1], ay);
                if (c2 == 0) atomicAdd(&g_gcnt[gprev], cnt);
            }
            ax = 0.f; ay = 0.f; cnt = 0; gprev = g;
        }
        float2 f = __half22float2(in2[(size_t)n * 32 + c2]);
        ax += f.x; ay += f.y; cnt++;
    }
    if (gprev >= 0) {
        atomicAdd(&g_gsum[gprev * NHID + c2 * 2], ax);
        atomicAdd(&g_gsum[gprev * NHID + c2 * 2 + 1], ay);
        if (c2 == 0) atomicAdd(&g_gcnt[gprev], cnt);
    }
}

__global__ void k_head(const float* __restrict__ Wl, const float* __restrict__ bl,
                       float* __restrict__ out) {
    int g = threadIdx.x;
    if (g >= NGRAPH) return;
    float cnt = fmaxf((float)g_gcnt[g], 1.f);
    float inv = 1.f / cnt;
    float l[NCLASS];
#pragma unroll
    for (int c = 0; c < NCLASS; c++) l[c] = bl[c];
    for (int k = 0; k < NHID; k++) {
        float p = g_gsum[g * NHID + k] * inv;
#pragma unroll
        for (int c = 0; c < NCLASS; c++) l[c] = fmaf(p, Wl[k * NCLASS + c], l[c]);
    }
    float m = l[0];
#pragma unroll
    for (int c = 1; c < NCLASS; c++) m = fmaxf(m, l[c]);
    float s = 0.f;
#pragma unroll
    for (int c = 0; c < NCLASS; c++) { l[c] = __expf(l[c] - m); s += l[c]; }
    float is = 1.f / s;
#pragma unroll
    for (int c = 0; c < NCLASS; c++) out[g * NCLASS + c] = l[c] * is;
}

// ---------------------------------------------------------------------------
extern "C" void kernel_launch(void* const* d_in, const int* in_sizes, int n_in,
                              void* d_out, int out_size) {
    const float* x     = (const float*)d_in[0];
    const int*   ei    = (const int*)d_in[1];
    const int*   batch = (const int*)d_in[2];
    const float* W1 = (const float*)d_in[3];
    const float* b1 = (const float*)d_in[4];
    const float* W2 = (const float*)d_in[5];
    const float* b2 = (const float*)d_in[6];
    const float* W3 = (const float*)d_in[7];
    const float* b3 = (const float*)d_in[8];
    const float* Wl = (const float*)d_in[9];
    const float* bl = (const float*)d_in[10];
    float* out = (float*)d_out;

    int N = in_sizes[0] / NFEAT;
    int E = in_sizes[1] / 2;

    const int T = 256;
    int nScanBlocks = (N + SCAN_B - 1) / SCAN_B;

    k_edge_prep<<<(E + T - 1) / T, T>>>(ei, E, N);
    k_scanA<<<nScanBlocks, SCAN_B>>>(N);
    k_scanB<<<1, 256>>>(nScanBlocks);
    k_scanC<<<nScanBlocks, SCAN_B>>>(N);
    k_csr_fill<<<(E + T - 1) / T, T>>>(ei, E, N);

    int gemmBlocks = (N + 63) / 64;
    int aggBlocks = (N * 32 + T - 1) / T;

    // Layer 1 (HMMA, K=128)
    k_gemm1<<<gemmBlocks, 128>>>(x, W1, N);
    k_agg<<<aggBlocks, T>>>(b1, N);
    // Layer 2 (HMMA, K=64)
    k_gemm23<<<gemmBlocks, 128>>>(W2, N);
    k_agg<<<aggBlocks, T>>>(b2, N);
    // Layer 3 (HMMA, K=64)
    k_gemm23<<<gemmBlocks, 128>>>(W3, N);
    k_agg<<<aggBlocks, T>>>(b3, N);

    // Pool + head
    k_pool<<<(((N + 3) / 4) * 32 + T - 1) / T, T>>>(batch, N);
    k_head<<<1, 64>>>(Wl, bl, out);
}